// round 1
// baseline (speedup 1.0000x reference)
#include <cuda_runtime.h>
#include <cstdint>
#include <cstddef>

#define DIMD   1024
#define TT     8192     // B*N = B*M rows
#define HD     64       // head dim
#define SEQ    2048

// ---------------- scratch (static device allocations are the sanctioned path) ----
__device__ float g_Qp[TT * DIMD];
__device__ float g_Kp[TT * DIMD];
__device__ float g_Vp[TT * DIMD];
__device__ float g_Oh[TT * DIMD];

// ---------------- f32x2 packed-FMA helpers (full-rate FFMA2 on sm_103a) ---------
__device__ __forceinline__ unsigned long long pk2(float x, float y) {
    unsigned long long r;
    asm("mov.b64 %0, {%1, %2};" : "=l"(r) : "f"(x), "f"(y));
    return r;
}
__device__ __forceinline__ float2 up2(unsigned long long c) {
    float2 u;
    asm("mov.b64 {%0, %1}, %2;" : "=f"(u.x), "=f"(u.y) : "l"(c));
    return u;
}
__device__ __forceinline__ void fma2(unsigned long long& c,
                                     unsigned long long a,
                                     unsigned long long b) {
    asm("fma.rn.f32x2 %0, %1, %2, %0;" : "+l"(c) : "l"(a), "l"(b));
}
__device__ __forceinline__ void mul2(unsigned long long& c, unsigned long long a) {
    asm("mul.rn.f32x2 %0, %0, %1;" : "+l"(c) : "l"(a));
}

// ================================================================================
// GEMM:  C[8192,1024] = X[8192,1024] @ W[1024,1024]^T (+bias) (+MODE1: relu+residual)
// 128x128 tile, BK=16, 256 threads, 8x8 per thread (as 8x4 f32x2 pairs),
// register-prefetch double buffering.
// ================================================================================
template <int MODE>
__global__ void __launch_bounds__(256)
gemm_kernel(const float* __restrict__ X, const float* __restrict__ W,
            const float* __restrict__ bias, const float* __restrict__ R,
            float* __restrict__ C)
{
    __shared__ float As[16][136];
    __shared__ float Bs[16][136];

    const int t    = threadIdx.x;
    const int bm   = blockIdx.y;
    const int bn   = blockIdx.x;
    const int arow = t >> 2;          // 0..63
    const int kq   = (t & 3) << 2;    // 0,4,8,12

    const float* Xp = X + (size_t)(bm * 128 + arow) * DIMD + kq;
    const float* Wp = W + (size_t)(bn * 128 + arow) * DIMD + kq;

    float4 xa0 = *(const float4*)(Xp);
    float4 xa1 = *(const float4*)(Xp + (size_t)64 * DIMD);
    float4 wb0 = *(const float4*)(Wp);
    float4 wb1 = *(const float4*)(Wp + (size_t)64 * DIMD);

    const int ty = t >> 4;   // 0..15, rows
    const int tx = t & 15;   // 0..15, cols

    unsigned long long acc[8][4];
    #pragma unroll
    for (int i = 0; i < 8; i++)
        #pragma unroll
        for (int j = 0; j < 4; j++) acc[i][j] = 0ull;

    for (int k0 = 0; k0 < DIMD; k0 += 16) {
        As[kq + 0][arow]      = xa0.x; As[kq + 1][arow]      = xa0.y;
        As[kq + 2][arow]      = xa0.z; As[kq + 3][arow]      = xa0.w;
        As[kq + 0][arow + 64] = xa1.x; As[kq + 1][arow + 64] = xa1.y;
        As[kq + 2][arow + 64] = xa1.z; As[kq + 3][arow + 64] = xa1.w;
        Bs[kq + 0][arow]      = wb0.x; Bs[kq + 1][arow]      = wb0.y;
        Bs[kq + 2][arow]      = wb0.z; Bs[kq + 3][arow]      = wb0.w;
        Bs[kq + 0][arow + 64] = wb1.x; Bs[kq + 1][arow + 64] = wb1.y;
        Bs[kq + 2][arow + 64] = wb1.z; Bs[kq + 3][arow + 64] = wb1.w;
        __syncthreads();

        if (k0 + 16 < DIMD) {
            xa0 = *(const float4*)(Xp + k0 + 16);
            xa1 = *(const float4*)(Xp + (size_t)64 * DIMD + k0 + 16);
            wb0 = *(const float4*)(Wp + k0 + 16);
            wb1 = *(const float4*)(Wp + (size_t)64 * DIMD + k0 + 16);
        }

        #pragma unroll
        for (int kk = 0; kk < 16; kk++) {
            float4 a0 = *(const float4*)&As[kk][ty * 8];
            float4 a1 = *(const float4*)&As[kk][ty * 8 + 4];
            float4 b0 = *(const float4*)&Bs[kk][tx * 8];
            float4 b1 = *(const float4*)&Bs[kk][tx * 8 + 4];
            unsigned long long bp0 = pk2(b0.x, b0.y);
            unsigned long long bp1 = pk2(b0.z, b0.w);
            unsigned long long bp2 = pk2(b1.x, b1.y);
            unsigned long long bp3 = pk2(b1.z, b1.w);
            float av[8] = {a0.x, a0.y, a0.z, a0.w, a1.x, a1.y, a1.z, a1.w};
            #pragma unroll
            for (int i = 0; i < 8; i++) {
                unsigned long long ad = pk2(av[i], av[i]);
                fma2(acc[i][0], ad, bp0);
                fma2(acc[i][1], ad, bp1);
                fma2(acc[i][2], ad, bp2);
                fma2(acc[i][3], ad, bp3);
            }
        }
        __syncthreads();
    }

    const int row0 = bm * 128 + ty * 8;
    const int col0 = bn * 128 + tx * 8;
    float bb[8];
    #pragma unroll
    for (int j = 0; j < 8; j++) bb[j] = bias[col0 + j];

    #pragma unroll
    for (int i = 0; i < 8; i++) {
        const int row = row0 + i;
        float o[8];
        #pragma unroll
        for (int j = 0; j < 4; j++) {
            float2 u = up2(acc[i][j]);
            o[2 * j] = u.x; o[2 * j + 1] = u.y;
        }
        #pragma unroll
        for (int j = 0; j < 8; j++) {
            float v = o[j] + bb[j];
            if (MODE == 1)
                v = fmaxf(v, 0.0f) + R[(size_t)row * DIMD + col0 + j];
            o[j] = v;
        }
        *(float4*)&C[(size_t)row * DIMD + col0]     = make_float4(o[0], o[1], o[2], o[3]);
        *(float4*)&C[(size_t)row * DIMD + col0 + 4] = make_float4(o[4], o[5], o[6], o[7]);
    }
}

// ================================================================================
// Flash attention per (b,h): Br=Bc=64, d=64. Online softmax, O += Q residual.
// Q/K tiles k-major with XOR swizzle (conflict-free float4 reads), V/P row-major.
// ================================================================================
__device__ __forceinline__ int swz(int k, int c) {
    return k * 64 + ((((c >> 2) ^ ((k >> 2) & 15)) << 2) | (c & 3));
}
__device__ __forceinline__ float4 ld_swz4(const float* base, int k, int c4) {
    return *(const float4*)(base + k * 64 + ((c4 ^ ((k >> 2) & 15)) << 2));
}

__global__ void __launch_bounds__(256)
attn_kernel(const float* __restrict__ Qp, const float* __restrict__ Kp,
            const float* __restrict__ Vp, float* __restrict__ Oh)
{
    extern __shared__ float smbuf[];
    float* QsT = smbuf;          // 64x64 swizzled (k-major)
    float* KsT = smbuf + 4096;   // 64x64 swizzled (k-major)
    float* Vs  = smbuf + 8192;   // 64x64 row-major (j, c)
    float* Ps  = smbuf + 12288;  // 64x64 row-major (r, j)

    const int t  = threadIdx.x;
    const int bh = blockIdx.y;
    const int b  = bh >> 4;
    const int h  = bh & 15;
    const int n0 = blockIdx.x * 64;
    const int ty = t >> 4;   // row group 0..15
    const int tx = t & 15;   // col group 0..15

    const size_t base = (size_t)b * SEQ * DIMD + (size_t)h * HD;

    // load Q tile (transposed+swizzled)
    {
        const int r  = t >> 2;
        const int kq = (t & 3) << 2;
        #pragma unroll
        for (int c = 0; c < 4; c++) {
            int k = kq + 16 * c;
            float4 v = *(const float4*)&Qp[base + (size_t)(n0 + r) * DIMD + k];
            QsT[swz(k + 0, r)] = v.x;
            QsT[swz(k + 1, r)] = v.y;
            QsT[swz(k + 2, r)] = v.z;
            QsT[swz(k + 3, r)] = v.w;
        }
    }

    float mrow[4], lrow[4];
    unsigned long long oa[4][2];
    #pragma unroll
    for (int i = 0; i < 4; i++) {
        mrow[i] = -1e30f; lrow[i] = 0.0f;
        oa[i][0] = 0ull;  oa[i][1] = 0ull;
    }
    __syncthreads();

    for (int m0 = 0; m0 < SEQ; m0 += 64) {
        // load K (swizzled) + V (row-major) chunk
        {
            const int r  = t >> 2;
            const int kq = (t & 3) << 2;
            #pragma unroll
            for (int c = 0; c < 4; c++) {
                int k = kq + 16 * c;
                float4 kv = *(const float4*)&Kp[base + (size_t)(m0 + r) * DIMD + k];
                KsT[swz(k + 0, r)] = kv.x;
                KsT[swz(k + 1, r)] = kv.y;
                KsT[swz(k + 2, r)] = kv.z;
                KsT[swz(k + 3, r)] = kv.w;
                float4 vv = *(const float4*)&Vp[base + (size_t)(m0 + r) * DIMD + k];
                *(float4*)&Vs[r * 64 + k] = vv;
            }
        }
        __syncthreads();

        // S = Q K^T  (4x4 per thread, packed pairs)
        unsigned long long s2[4][2];
        #pragma unroll
        for (int i = 0; i < 4; i++) { s2[i][0] = 0ull; s2[i][1] = 0ull; }

        #pragma unroll 8
        for (int k = 0; k < 64; k++) {
            float4 qa = ld_swz4(QsT, k, ty);
            float4 kb = ld_swz4(KsT, k, tx);
            unsigned long long kp0 = pk2(kb.x, kb.y);
            unsigned long long kp1 = pk2(kb.z, kb.w);
            float qv[4] = {qa.x, qa.y, qa.z, qa.w};
            #pragma unroll
            for (int i = 0; i < 4; i++) {
                unsigned long long qd = pk2(qv[i], qv[i]);
                fma2(s2[i][0], qd, kp0);
                fma2(s2[i][1], qd, kp1);
            }
        }

        // online softmax update (scale = 1/sqrt(1024) = 1/32)
        #pragma unroll
        for (int i = 0; i < 4; i++) {
            float2 u0 = up2(s2[i][0]);
            float2 u1 = up2(s2[i][1]);
            float s0 = u0.x * 0.03125f, s1v = u0.y * 0.03125f;
            float s2v = u1.x * 0.03125f, s3v = u1.y * 0.03125f;

            float mx = fmaxf(fmaxf(s0, s1v), fmaxf(s2v, s3v));
            mx = fmaxf(mx, __shfl_xor_sync(0xffffffffu, mx, 1));
            mx = fmaxf(mx, __shfl_xor_sync(0xffffffffu, mx, 2));
            mx = fmaxf(mx, __shfl_xor_sync(0xffffffffu, mx, 4));
            mx = fmaxf(mx, __shfl_xor_sync(0xffffffffu, mx, 8));

            float mnew = fmaxf(mrow[i], mx);
            float sc   = __expf(mrow[i] - mnew);
            float p0 = __expf(s0 - mnew);
            float p1 = __expf(s1v - mnew);
            float p2 = __expf(s2v - mnew);
            float p3 = __expf(s3v - mnew);
            float rs = (p0 + p1) + (p2 + p3);
            rs += __shfl_xor_sync(0xffffffffu, rs, 1);
            rs += __shfl_xor_sync(0xffffffffu, rs, 2);
            rs += __shfl_xor_sync(0xffffffffu, rs, 4);
            rs += __shfl_xor_sync(0xffffffffu, rs, 8);

            lrow[i] = lrow[i] * sc + rs;
            mrow[i] = mnew;

            unsigned long long scp = pk2(sc, sc);
            mul2(oa[i][0], scp);
            mul2(oa[i][1], scp);

            *(float4*)&Ps[(ty * 4 + i) * 64 + tx * 4] = make_float4(p0, p1, p2, p3);
        }
        __syncthreads();

        // O += P @ V
        #pragma unroll 4
        for (int jb = 0; jb < 16; jb++) {
            float pv[4][4];
            #pragma unroll
            for (int i = 0; i < 4; i++) {
                float4 x = *(const float4*)&Ps[(ty * 4 + i) * 64 + jb * 4];
                pv[i][0] = x.x; pv[i][1] = x.y; pv[i][2] = x.z; pv[i][3] = x.w;
            }
            #pragma unroll
            for (int jj = 0; jj < 4; jj++) {
                float4 vv = *(const float4*)&Vs[(jb * 4 + jj) * 64 + tx * 4];
                unsigned long long v0 = pk2(vv.x, vv.y);
                unsigned long long v1 = pk2(vv.z, vv.w);
                #pragma unroll
                for (int i = 0; i < 4; i++) {
                    unsigned long long pd = pk2(pv[i][jj], pv[i][jj]);
                    fma2(oa[i][0], pd, v0);
                    fma2(oa[i][1], pd, v1);
                }
            }
        }
        __syncthreads();
    }

    // finalize: O = acc / l + Q (residual), write out
    #pragma unroll
    for (int i = 0; i < 4; i++) {
        const int r = ty * 4 + i;
        float inv = 1.0f / lrow[i];
        float2 u0 = up2(oa[i][0]);
        float2 u1 = up2(oa[i][1]);
        float o0 = u0.x * inv + QsT[swz(tx * 4 + 0, r)];
        float o1 = u0.y * inv + QsT[swz(tx * 4 + 1, r)];
        float o2 = u1.x * inv + QsT[swz(tx * 4 + 2, r)];
        float o3 = u1.y * inv + QsT[swz(tx * 4 + 3, r)];
        *(float4*)&Oh[base + (size_t)(n0 + r) * DIMD + tx * 4] =
            make_float4(o0, o1, o2, o3);
    }
}

// ================================================================================
extern "C" void kernel_launch(void* const* d_in, const int* in_sizes, int n_in,
                              void* d_out, int out_size)
{
    const float* Q  = (const float*)d_in[0];
    const float* K  = (const float*)d_in[1];
    const float* Wq = (const float*)d_in[2];
    const float* bq = (const float*)d_in[3];
    const float* Wk = (const float*)d_in[4];
    const float* bk = (const float*)d_in[5];
    const float* Wv = (const float*)d_in[6];
    const float* bv = (const float*)d_in[7];
    const float* Wo = (const float*)d_in[8];
    const float* bo = (const float*)d_in[9];
    float* out = (float*)d_out;

    float *Qp, *Kp, *Vp, *Oh;
    cudaGetSymbolAddress((void**)&Qp, g_Qp);
    cudaGetSymbolAddress((void**)&Kp, g_Kp);
    cudaGetSymbolAddress((void**)&Vp, g_Vp);
    cudaGetSymbolAddress((void**)&Oh, g_Oh);

    cudaFuncSetAttribute(attn_kernel,
                         cudaFuncAttributeMaxDynamicSharedMemorySize, 65536);

    dim3 gg(8, 64);
    dim3 gb(256);
    gemm_kernel<0><<<gg, gb>>>(Q, Wq, bq, nullptr, Qp);
    gemm_kernel<0><<<gg, gb>>>(K, Wk, bk, nullptr, Kp);
    gemm_kernel<0><<<gg, gb>>>(K, Wv, bv, nullptr, Vp);
    attn_kernel<<<dim3(32, 64), gb, 65536>>>(Qp, Kp, Vp, Oh);
    gemm_kernel<1><<<gg, gb>>>(Oh, Wo, bo, Oh, out);
}

// round 3
// speedup vs baseline: 1.3326x; 1.3326x over previous
#include <cuda_runtime.h>
#include <cuda_bf16.h>
#include <cstdint>
#include <cstddef>

#define DIMD   1024
#define TT     8192     // B*N = B*M rows
#define HD     64       // head dim
#define SEQ    2048

// ---------------- scratch ----------------
__device__ float g_Qp[TT * DIMD];
__device__ float g_Kp[TT * DIMD];
__device__ float g_Vp[TT * DIMD];
__device__ float g_Oh[TT * DIMD];

// =========================== helpers =================================
__device__ __forceinline__ uint32_t smem_u32(const void* p) {
    uint32_t a;
    asm("{ .reg .u64 t; cvta.to.shared.u64 t, %1; cvt.u32.u64 %0, t; }"
        : "=r"(a) : "l"(p));
    return a;
}

// ---------------- f32x2 packed-FMA helpers (attention kernel) -------------------
__device__ __forceinline__ unsigned long long pk2(float x, float y) {
    unsigned long long r;
    asm("mov.b64 %0, {%1, %2};" : "=l"(r) : "f"(x), "f"(y));
    return r;
}
__device__ __forceinline__ float2 up2(unsigned long long c) {
    float2 u;
    asm("mov.b64 {%0, %1}, %2;" : "=f"(u.x), "=f"(u.y) : "l"(c));
    return u;
}
__device__ __forceinline__ void fma2(unsigned long long& c,
                                     unsigned long long a,
                                     unsigned long long b) {
    asm("fma.rn.f32x2 %0, %1, %2, %0;" : "+l"(c) : "l"(a), "l"(b));
}
__device__ __forceinline__ void mul2(unsigned long long& c, unsigned long long a) {
    asm("mul.rn.f32x2 %0, %0, %1;" : "+l"(c) : "l"(a));
}

// ---------------- tensor-core (legacy mma.sync, bf16) helpers -------------------
#define LDSM_X4(R0, R1, R2, R3, addr) \
    asm volatile("ldmatrix.sync.aligned.m8n8.x4.shared.b16 {%0,%1,%2,%3}, [%4];" \
                 : "=r"(R0), "=r"(R1), "=r"(R2), "=r"(R3) : "r"(addr))

#define MMA_BF16(c, a, b0, b1) \
    asm volatile("mma.sync.aligned.m16n8k16.row.col.f32.bf16.bf16.f32 " \
                 "{%0,%1,%2,%3}, {%4,%5,%6,%7}, {%8,%9}, {%0,%1,%2,%3};" \
                 : "+f"((c)[0]), "+f"((c)[1]), "+f"((c)[2]), "+f"((c)[3]) \
                 : "r"((a)[0]), "r"((a)[1]), "r"((a)[2]), "r"((a)[3]), \
                   "r"(b0), "r"(b1))

// split fp32 -> (hi, lo) bf16 pair; 8 floats -> 4 packed hi + 4 packed lo
__device__ __forceinline__ void cvt8(const float* f, uint32_t* hi, uint32_t* lo) {
    #pragma unroll
    for (int i = 0; i < 4; i++) {
        float x0 = f[2 * i], x1 = f[2 * i + 1];
        __nv_bfloat16 h0 = __float2bfloat16_rn(x0);
        __nv_bfloat16 h1 = __float2bfloat16_rn(x1);
        __nv_bfloat16 l0 = __float2bfloat16_rn(x0 - __bfloat162float(h0));
        __nv_bfloat16 l1 = __float2bfloat16_rn(x1 - __bfloat162float(h1));
        __nv_bfloat162 hh = __nv_bfloat162(h0, h1);
        __nv_bfloat162 ll = __nv_bfloat162(l0, l1);
        hi[i] = *(uint32_t*)&hh;
        lo[i] = *(uint32_t*)&ll;
    }
}

// swizzled smem address: 128B rows, 8 chunks of 16B, chunk c XOR (r&7)
__device__ __forceinline__ uint32_t sw_addr(uint32_t base, int r, int c) {
    return base + (uint32_t)(r * 128) + (uint32_t)(((c ^ (r & 7)) & 7) << 4);
}

// ================================================================================
// bf16 3-pass split-compensated tensor-core GEMM:
//   C[8192,1024] = X[8192,1024] @ W[1024,1024]^T (+bias) (+MODE1: relu+residual)
// 128x128 tile, BK=32, 256 threads (8 warps, 2m x 4n), warp tile 64x32.
// ================================================================================
#define GEMM_SMEM (2 * 32768)

template <int MODE>
__global__ void __launch_bounds__(256)
gemm_mma(const float* __restrict__ X, const float* __restrict__ W,
         const float* __restrict__ bias, const float* __restrict__ R,
         float* __restrict__ C)
{
    extern __shared__ char sm[];
    const uint32_t sb = smem_u32(sm);

    const int t    = threadIdx.x;
    const int w    = t >> 5;
    const int lane = t & 31;
    const int wm   = w >> 2;    // 0..1  (64-row slab)
    const int wn   = w & 3;     // 0..3  (32-col slab)
    const int bn   = blockIdx.x;
    const int bm   = blockIdx.y;

    float acc[4][4][4];
    #pragma unroll
    for (int mi = 0; mi < 4; mi++)
        #pragma unroll
        for (int ni = 0; ni < 4; ni++)
            #pragma unroll
            for (int q = 0; q < 4; q++) acc[mi][ni][q] = 0.0f;

    // staging registers for one k-chunk (A and B, 2 segments each of 8 floats)
    float stA[2][8], stB[2][8];

    const int r0i  = t >> 2;         // 0..63 base row (2 segs -> +0, +64)? no: idx scheme below
    // staging index scheme: idx = t + 256*s, r = idx>>2 (0..127), seg = idx&3

    // prefetch chunk 0
    #pragma unroll
    for (int s = 0; s < 2; s++) {
        int idx = t + 256 * s;
        int r = idx >> 2, seg = idx & 3;
        const float* pA = X + (size_t)(bm * 128 + r) * DIMD + seg * 8;
        const float* pB = W + (size_t)(bn * 128 + r) * DIMD + seg * 8;
        *(float4*)&stA[s][0] = *(const float4*)(pA);
        *(float4*)&stA[s][4] = *(const float4*)(pA + 4);
        *(float4*)&stB[s][0] = *(const float4*)(pB);
        *(float4*)&stB[s][4] = *(const float4*)(pB + 4);
    }

    const int rin = lane & 15;
    const int hb  = lane >> 4;

    for (int ch = 0; ch < 32; ch++) {
        const uint32_t Ab = sb + (uint32_t)(ch & 1) * 32768u;
        const uint32_t Bb = Ab + 16384u;

        // store staged chunk into swizzled bf16 smem (hi chunks 0-3, lo chunks 4-7)
        #pragma unroll
        for (int s = 0; s < 2; s++) {
            int idx = t + 256 * s;
            int r = idx >> 2, seg = idx & 3;
            uint32_t hi[4], lo[4];
            cvt8(stA[s], hi, lo);
            asm volatile("st.shared.v4.b32 [%0], {%1,%2,%3,%4};"
                         :: "r"(sw_addr(Ab, r, seg)),
                            "r"(hi[0]), "r"(hi[1]), "r"(hi[2]), "r"(hi[3]));
            asm volatile("st.shared.v4.b32 [%0], {%1,%2,%3,%4};"
                         :: "r"(sw_addr(Ab, r, seg + 4)),
                            "r"(lo[0]), "r"(lo[1]), "r"(lo[2]), "r"(lo[3]));
            cvt8(stB[s], hi, lo);
            asm volatile("st.shared.v4.b32 [%0], {%1,%2,%3,%4};"
                         :: "r"(sw_addr(Bb, r, seg)),
                            "r"(hi[0]), "r"(hi[1]), "r"(hi[2]), "r"(hi[3]));
            asm volatile("st.shared.v4.b32 [%0], {%1,%2,%3,%4};"
                         :: "r"(sw_addr(Bb, r, seg + 4)),
                            "r"(lo[0]), "r"(lo[1]), "r"(lo[2]), "r"(lo[3]));
        }
        __syncthreads();

        // prefetch next chunk
        if (ch + 1 < 32) {
            const int k0 = (ch + 1) * 32;
            #pragma unroll
            for (int s = 0; s < 2; s++) {
                int idx = t + 256 * s;
                int r = idx >> 2, seg = idx & 3;
                const float* pA = X + (size_t)(bm * 128 + r) * DIMD + k0 + seg * 8;
                const float* pB = W + (size_t)(bn * 128 + r) * DIMD + k0 + seg * 8;
                *(float4*)&stA[s][0] = *(const float4*)(pA);
                *(float4*)&stA[s][4] = *(const float4*)(pA + 4);
                *(float4*)&stB[s][0] = *(const float4*)(pB);
                *(float4*)&stB[s][4] = *(const float4*)(pB + 4);
            }
        }

        // MMA over this chunk: 2 k16-steps, 3 passes each
        #pragma unroll
        for (int ks = 0; ks < 2; ks++) {
            const int chi = ks * 2 + hb;   // hi-plane logical chunk for this lane

            uint32_t afr[4][4];
            #pragma unroll
            for (int mi = 0; mi < 4; mi++)
                LDSM_X4(afr[mi][0], afr[mi][1], afr[mi][2], afr[mi][3],
                        sw_addr(Ab, wm * 64 + mi * 16 + rin, chi));

            uint32_t bh[2][4];
            #pragma unroll
            for (int pi = 0; pi < 2; pi++)
                LDSM_X4(bh[pi][0], bh[pi][1], bh[pi][2], bh[pi][3],
                        sw_addr(Bb, wn * 32 + pi * 16 + rin, chi));

            // pass 1: Ahi * Bhi
            #pragma unroll
            for (int mi = 0; mi < 4; mi++)
                #pragma unroll
                for (int ni = 0; ni < 4; ni++)
                    MMA_BF16(acc[mi][ni], afr[mi],
                             bh[ni >> 1][ni & 1], bh[ni >> 1][(ni & 1) + 2]);

            // pass 2: Ahi * Blo
            uint32_t bl[2][4];
            #pragma unroll
            for (int pi = 0; pi < 2; pi++)
                LDSM_X4(bl[pi][0], bl[pi][1], bl[pi][2], bl[pi][3],
                        sw_addr(Bb, wn * 32 + pi * 16 + rin, chi + 4));
            #pragma unroll
            for (int mi = 0; mi < 4; mi++)
                #pragma unroll
                for (int ni = 0; ni < 4; ni++)
                    MMA_BF16(acc[mi][ni], afr[mi],
                             bl[ni >> 1][ni & 1], bl[ni >> 1][(ni & 1) + 2]);

            // pass 3: Alo * Bhi (overwrite A frags)
            #pragma unroll
            for (int mi = 0; mi < 4; mi++)
                LDSM_X4(afr[mi][0], afr[mi][1], afr[mi][2], afr[mi][3],
                        sw_addr(Ab, wm * 64 + mi * 16 + rin, chi + 4));
            #pragma unroll
            for (int mi = 0; mi < 4; mi++)
                #pragma unroll
                for (int ni = 0; ni < 4; ni++)
                    MMA_BF16(acc[mi][ni], afr[mi],
                             bh[ni >> 1][ni & 1], bh[ni >> 1][(ni & 1) + 2]);
        }
    }

    // ------------------------- epilogue -------------------------
    const int rbase = bm * 128 + wm * 64;
    const int cbase = bn * 128 + wn * 32;
    float bb[4][2];
    #pragma unroll
    for (int ni = 0; ni < 4; ni++) {
        int c0 = cbase + ni * 8 + (lane & 3) * 2;
        bb[ni][0] = bias[c0];
        bb[ni][1] = bias[c0 + 1];
    }

    #pragma unroll
    for (int mi = 0; mi < 4; mi++) {
        #pragma unroll
        for (int ni = 0; ni < 4; ni++) {
            int r0 = rbase + mi * 16 + (lane >> 2);
            int c0 = cbase + ni * 8 + (lane & 3) * 2;
            float o0 = acc[mi][ni][0] + bb[ni][0];
            float o1 = acc[mi][ni][1] + bb[ni][1];
            float o2 = acc[mi][ni][2] + bb[ni][0];
            float o3 = acc[mi][ni][3] + bb[ni][1];
            if (MODE == 1) {
                float2 ra = *(const float2*)&R[(size_t)r0 * DIMD + c0];
                float2 rb = *(const float2*)&R[(size_t)(r0 + 8) * DIMD + c0];
                o0 = fmaxf(o0, 0.0f) + ra.x;
                o1 = fmaxf(o1, 0.0f) + ra.y;
                o2 = fmaxf(o2, 0.0f) + rb.x;
                o3 = fmaxf(o3, 0.0f) + rb.y;
            }
            *(float2*)&C[(size_t)r0 * DIMD + c0]       = make_float2(o0, o1);
            *(float2*)&C[(size_t)(r0 + 8) * DIMD + c0] = make_float2(o2, o3);
        }
    }
}

// ================================================================================
// Flash attention per (b,h): Br=Bc=64, d=64. Online softmax, O += Q residual.
// (unchanged from passing Round-1 kernel; FFMA2 path)
// ================================================================================
__device__ __forceinline__ int swz(int k, int c) {
    return k * 64 + ((((c >> 2) ^ ((k >> 2) & 15)) << 2) | (c & 3));
}
__device__ __forceinline__ float4 ld_swz4(const float* base, int k, int c4) {
    return *(const float4*)(base + k * 64 + ((c4 ^ ((k >> 2) & 15)) << 2));
}

__global__ void __launch_bounds__(256)
attn_kernel(const float* __restrict__ Qp, const float* __restrict__ Kp,
            const float* __restrict__ Vp, float* __restrict__ Oh)
{
    extern __shared__ float smbuf[];
    float* QsT = smbuf;          // 64x64 swizzled (k-major)
    float* KsT = smbuf + 4096;   // 64x64 swizzled (k-major)
    float* Vs  = smbuf + 8192;   // 64x64 row-major (j, c)
    float* Ps  = smbuf + 12288;  // 64x64 row-major (r, j)

    const int t  = threadIdx.x;
    const int bh = blockIdx.y;
    const int b  = bh >> 4;
    const int h  = bh & 15;
    const int n0 = blockIdx.x * 64;
    const int ty = t >> 4;
    const int tx = t & 15;

    const size_t base = (size_t)b * SEQ * DIMD + (size_t)h * HD;

    {
        const int r  = t >> 2;
        const int kq = (t & 3) << 2;
        #pragma unroll
        for (int c = 0; c < 4; c++) {
            int k = kq + 16 * c;
            float4 v = *(const float4*)&Qp[base + (size_t)(n0 + r) * DIMD + k];
            QsT[swz(k + 0, r)] = v.x;
            QsT[swz(k + 1, r)] = v.y;
            QsT[swz(k + 2, r)] = v.z;
            QsT[swz(k + 3, r)] = v.w;
        }
    }

    float mrow[4], lrow[4];
    unsigned long long oa[4][2];
    #pragma unroll
    for (int i = 0; i < 4; i++) {
        mrow[i] = -1e30f; lrow[i] = 0.0f;
        oa[i][0] = 0ull;  oa[i][1] = 0ull;
    }
    __syncthreads();

    for (int m0 = 0; m0 < SEQ; m0 += 64) {
        {
            const int r  = t >> 2;
            const int kq = (t & 3) << 2;
            #pragma unroll
            for (int c = 0; c < 4; c++) {
                int k = kq + 16 * c;
                float4 kv = *(const float4*)&Kp[base + (size_t)(m0 + r) * DIMD + k];
                KsT[swz(k + 0, r)] = kv.x;
                KsT[swz(k + 1, r)] = kv.y;
                KsT[swz(k + 2, r)] = kv.z;
                KsT[swz(k + 3, r)] = kv.w;
                float4 vv = *(const float4*)&Vp[base + (size_t)(m0 + r) * DIMD + k];
                *(float4*)&Vs[r * 64 + k] = vv;
            }
        }
        __syncthreads();

        unsigned long long s2[4][2];
        #pragma unroll
        for (int i = 0; i < 4; i++) { s2[i][0] = 0ull; s2[i][1] = 0ull; }

        #pragma unroll 8
        for (int k = 0; k < 64; k++) {
            float4 qa = ld_swz4(QsT, k, ty);
            float4 kb = ld_swz4(KsT, k, tx);
            unsigned long long kp0 = pk2(kb.x, kb.y);
            unsigned long long kp1 = pk2(kb.z, kb.w);
            float qv[4] = {qa.x, qa.y, qa.z, qa.w};
            #pragma unroll
            for (int i = 0; i < 4; i++) {
                unsigned long long qd = pk2(qv[i], qv[i]);
                fma2(s2[i][0], qd, kp0);
                fma2(s2[i][1], qd, kp1);
            }
        }

        #pragma unroll
        for (int i = 0; i < 4; i++) {
            float2 u0 = up2(s2[i][0]);
            float2 u1 = up2(s2[i][1]);
            float s0 = u0.x * 0.03125f, s1v = u0.y * 0.03125f;
            float s2v = u1.x * 0.03125f, s3v = u1.y * 0.03125f;

            float mx = fmaxf(fmaxf(s0, s1v), fmaxf(s2v, s3v));
            mx = fmaxf(mx, __shfl_xor_sync(0xffffffffu, mx, 1));
            mx = fmaxf(mx, __shfl_xor_sync(0xffffffffu, mx, 2));
            mx = fmaxf(mx, __shfl_xor_sync(0xffffffffu, mx, 4));
            mx = fmaxf(mx, __shfl_xor_sync(0xffffffffu, mx, 8));

            float mnew = fmaxf(mrow[i], mx);
            float sc   = __expf(mrow[i] - mnew);
            float p0 = __expf(s0 - mnew);
            float p1 = __expf(s1v - mnew);
            float p2 = __expf(s2v - mnew);
            float p3 = __expf(s3v - mnew);
            float rs = (p0 + p1) + (p2 + p3);
            rs += __shfl_xor_sync(0xffffffffu, rs, 1);
            rs += __shfl_xor_sync(0xffffffffu, rs, 2);
            rs += __shfl_xor_sync(0xffffffffu, rs, 4);
            rs += __shfl_xor_sync(0xffffffffu, rs, 8);

            lrow[i] = lrow[i] * sc + rs;
            mrow[i] = mnew;

            unsigned long long scp = pk2(sc, sc);
            mul2(oa[i][0], scp);
            mul2(oa[i][1], scp);

            *(float4*)&Ps[(ty * 4 + i) * 64 + tx * 4] = make_float4(p0, p1, p2, p3);
        }
        __syncthreads();

        #pragma unroll 4
        for (int jb = 0; jb < 16; jb++) {
            float pv[4][4];
            #pragma unroll
            for (int i = 0; i < 4; i++) {
                float4 x = *(const float4*)&Ps[(ty * 4 + i) * 64 + jb * 4];
                pv[i][0] = x.x; pv[i][1] = x.y; pv[i][2] = x.z; pv[i][3] = x.w;
            }
            #pragma unroll
            for (int jj = 0; jj < 4; jj++) {
                float4 vv = *(const float4*)&Vs[(jb * 4 + jj) * 64 + tx * 4];
                unsigned long long v0 = pk2(vv.x, vv.y);
                unsigned long long v1 = pk2(vv.z, vv.w);
                #pragma unroll
                for (int i = 0; i < 4; i++) {
                    unsigned long long pd = pk2(pv[i][jj], pv[i][jj]);
                    fma2(oa[i][0], pd, v0);
                    fma2(oa[i][1], pd, v1);
                }
            }
        }
        __syncthreads();
    }

    #pragma unroll
    for (int i = 0; i < 4; i++) {
        const int r = ty * 4 + i;
        float inv = 1.0f / lrow[i];
        float2 u0 = up2(oa[i][0]);
        float2 u1 = up2(oa[i][1]);
        float o0 = u0.x * inv + QsT[swz(tx * 4 + 0, r)];
        float o1 = u0.y * inv + QsT[swz(tx * 4 + 1, r)];
        float o2 = u1.x * inv + QsT[swz(tx * 4 + 2, r)];
        float o3 = u1.y * inv + QsT[swz(tx * 4 + 3, r)];
        *(float4*)&Oh[base + (size_t)(n0 + r) * DIMD + tx * 4] =
            make_float4(o0, o1, o2, o3);
    }
}

// ================================================================================
extern "C" void kernel_launch(void* const* d_in, const int* in_sizes, int n_in,
                              void* d_out, int out_size)
{
    const float* Q  = (const float*)d_in[0];
    const float* K  = (const float*)d_in[1];
    const float* Wq = (const float*)d_in[2];
    const float* bq = (const float*)d_in[3];
    const float* Wk = (const float*)d_in[4];
    const float* bk = (const float*)d_in[5];
    const float* Wv = (const float*)d_in[6];
    const float* bv = (const float*)d_in[7];
    const float* Wo = (const float*)d_in[8];
    const float* bo = (const float*)d_in[9];
    float* out = (float*)d_out;

    float *Qp, *Kp, *Vp, *Oh;
    cudaGetSymbolAddress((void**)&Qp, g_Qp);
    cudaGetSymbolAddress((void**)&Kp, g_Kp);
    cudaGetSymbolAddress((void**)&Vp, g_Vp);
    cudaGetSymbolAddress((void**)&Oh, g_Oh);

    cudaFuncSetAttribute(attn_kernel,
                         cudaFuncAttributeMaxDynamicSharedMemorySize, 65536);
    cudaFuncSetAttribute(gemm_mma<0>,
                         cudaFuncAttributeMaxDynamicSharedMemorySize, GEMM_SMEM);
    cudaFuncSetAttribute(gemm_mma<1>,
                         cudaFuncAttributeMaxDynamicSharedMemorySize, GEMM_SMEM);

    dim3 gg(8, 64);   // (N blocks, M blocks)
    gemm_mma<0><<<gg, 256, GEMM_SMEM>>>(Q, Wq, bq, nullptr, Qp);
    gemm_mma<0><<<gg, 256, GEMM_SMEM>>>(K, Wk, bk, nullptr, Kp);
    gemm_mma<0><<<gg, 256, GEMM_SMEM>>>(K, Wv, bv, nullptr, Vp);
    attn_kernel<<<dim3(32, 64), 256, 65536>>>(Qp, Kp, Vp, Oh);
    gemm_mma<1><<<gg, 256, GEMM_SMEM>>>(Oh, Wo, bo, Oh, out);
}

// round 7
// speedup vs baseline: 2.8095x; 2.1083x over previous
#include <cuda_runtime.h>
#include <cuda_bf16.h>
#include <cstdint>
#include <cstddef>

#define DIMD   1024
#define TT     8192     // B*N = B*M rows
#define HD     64       // head dim
#define SEQ    2048

// ---------------- scratch ----------------
__device__ float g_Qp[TT * DIMD];
__device__ float g_Kp[TT * DIMD];
__device__ float g_Vp[TT * DIMD];
__device__ float g_Oh[TT * DIMD];

// =========================== helpers =================================
__device__ __forceinline__ uint32_t smem_u32(const void* p) {
    uint32_t a;
    asm("{ .reg .u64 t; cvta.to.shared.u64 t, %1; cvt.u32.u64 %0, t; }"
        : "=r"(a) : "l"(p));
    return a;
}

// ---------------- tensor-core (legacy mma.sync, bf16) helpers -------------------
#define LDSM_X4(R0, R1, R2, R3, addr) \
    asm volatile("ldmatrix.sync.aligned.m8n8.x4.shared.b16 {%0,%1,%2,%3}, [%4];" \
                 : "=r"(R0), "=r"(R1), "=r"(R2), "=r"(R3) : "r"(addr))

#define MMA_BF16(c, a, b0, b1) \
    asm volatile("mma.sync.aligned.m16n8k16.row.col.f32.bf16.bf16.f32 " \
                 "{%0,%1,%2,%3}, {%4,%5,%6,%7}, {%8,%9}, {%0,%1,%2,%3};" \
                 : "+f"((c)[0]), "+f"((c)[1]), "+f"((c)[2]), "+f"((c)[3]) \
                 : "r"((a)[0]), "r"((a)[1]), "r"((a)[2]), "r"((a)[3]), \
                   "r"(b0), "r"(b1))

// pack two fp32 -> bf16x2 (lo = element 0, hi = element 1)
__device__ __forceinline__ uint32_t pkbf(float lo, float hi) {
    uint32_t d;
    asm("cvt.rn.bf16x2.f32 %0, %1, %2;" : "=r"(d) : "f"(hi), "f"(lo));
    return d;
}

// split fp32 -> (hi, lo) bf16 pair; 8 floats -> 4 packed hi + 4 packed lo
__device__ __forceinline__ void cvt8(const float* f, uint32_t* hi, uint32_t* lo) {
    #pragma unroll
    for (int i = 0; i < 4; i++) {
        float x0 = f[2 * i], x1 = f[2 * i + 1];
        __nv_bfloat16 h0 = __float2bfloat16_rn(x0);
        __nv_bfloat16 h1 = __float2bfloat16_rn(x1);
        __nv_bfloat16 l0 = __float2bfloat16_rn(x0 - __bfloat162float(h0));
        __nv_bfloat16 l1 = __float2bfloat16_rn(x1 - __bfloat162float(h1));
        __nv_bfloat162 hh = __nv_bfloat162(h0, h1);
        __nv_bfloat162 ll = __nv_bfloat162(l0, l1);
        hi[i] = *(uint32_t*)&hh;
        lo[i] = *(uint32_t*)&ll;
    }
}

// swizzled smem address: 128B rows, 8 chunks of 16B, chunk c XOR (r&7)
__device__ __forceinline__ uint32_t sw_addr(uint32_t base, int r, int c) {
    return base + (uint32_t)(r * 128) + (uint32_t)(((c ^ (r & 7)) & 7) << 4);
}

// store 8 bf16 (one 16B chunk) from two float4
__device__ __forceinline__ void stb16(uint32_t a, float4 f0, float4 f1) {
    uint32_t r0 = pkbf(f0.x, f0.y), r1 = pkbf(f0.z, f0.w);
    uint32_t r2 = pkbf(f1.x, f1.y), r3 = pkbf(f1.z, f1.w);
    asm volatile("st.shared.v4.b32 [%0], {%1,%2,%3,%4};"
                 :: "r"(a), "r"(r0), "r"(r1), "r"(r2), "r"(r3));
}

// ================================================================================
// bf16 3-pass split-compensated tensor-core GEMM (unchanged from R3, passing):
//   C[8192,1024] = X[8192,1024] @ W[1024,1024]^T (+bias) (+MODE1: relu+residual)
// ================================================================================
#define GEMM_SMEM (2 * 32768)

template <int MODE>
__global__ void __launch_bounds__(256)
gemm_mma(const float* __restrict__ X, const float* __restrict__ W,
         const float* __restrict__ bias, const float* __restrict__ R,
         float* __restrict__ C)
{
    extern __shared__ char sm[];
    const uint32_t sb = smem_u32(sm);

    const int t    = threadIdx.x;
    const int w    = t >> 5;
    const int lane = t & 31;
    const int wm   = w >> 2;
    const int wn   = w & 3;
    const int bn   = blockIdx.x;
    const int bm   = blockIdx.y;

    float acc[4][4][4];
    #pragma unroll
    for (int mi = 0; mi < 4; mi++)
        #pragma unroll
        for (int ni = 0; ni < 4; ni++)
            #pragma unroll
            for (int q = 0; q < 4; q++) acc[mi][ni][q] = 0.0f;

    float stA[2][8], stB[2][8];

    #pragma unroll
    for (int s = 0; s < 2; s++) {
        int idx = t + 256 * s;
        int r = idx >> 2, seg = idx & 3;
        const float* pA = X + (size_t)(bm * 128 + r) * DIMD + seg * 8;
        const float* pB = W + (size_t)(bn * 128 + r) * DIMD + seg * 8;
        *(float4*)&stA[s][0] = *(const float4*)(pA);
        *(float4*)&stA[s][4] = *(const float4*)(pA + 4);
        *(float4*)&stB[s][0] = *(const float4*)(pB);
        *(float4*)&stB[s][4] = *(const float4*)(pB + 4);
    }

    const int rin = lane & 15;
    const int hb  = lane >> 4;

    for (int ch = 0; ch < 32; ch++) {
        const uint32_t Ab = sb + (uint32_t)(ch & 1) * 32768u;
        const uint32_t Bb = Ab + 16384u;

        #pragma unroll
        for (int s = 0; s < 2; s++) {
            int idx = t + 256 * s;
            int r = idx >> 2, seg = idx & 3;
            uint32_t hi[4], lo[4];
            cvt8(stA[s], hi, lo);
            asm volatile("st.shared.v4.b32 [%0], {%1,%2,%3,%4};"
                         :: "r"(sw_addr(Ab, r, seg)),
                            "r"(hi[0]), "r"(hi[1]), "r"(hi[2]), "r"(hi[3]));
            asm volatile("st.shared.v4.b32 [%0], {%1,%2,%3,%4};"
                         :: "r"(sw_addr(Ab, r, seg + 4)),
                            "r"(lo[0]), "r"(lo[1]), "r"(lo[2]), "r"(lo[3]));
            cvt8(stB[s], hi, lo);
            asm volatile("st.shared.v4.b32 [%0], {%1,%2,%3,%4};"
                         :: "r"(sw_addr(Bb, r, seg)),
                            "r"(hi[0]), "r"(hi[1]), "r"(hi[2]), "r"(hi[3]));
            asm volatile("st.shared.v4.b32 [%0], {%1,%2,%3,%4};"
                         :: "r"(sw_addr(Bb, r, seg + 4)),
                            "r"(lo[0]), "r"(lo[1]), "r"(lo[2]), "r"(lo[3]));
        }
        __syncthreads();

        if (ch + 1 < 32) {
            const int k0 = (ch + 1) * 32;
            #pragma unroll
            for (int s = 0; s < 2; s++) {
                int idx = t + 256 * s;
                int r = idx >> 2, seg = idx & 3;
                const float* pA = X + (size_t)(bm * 128 + r) * DIMD + k0 + seg * 8;
                const float* pB = W + (size_t)(bn * 128 + r) * DIMD + k0 + seg * 8;
                *(float4*)&stA[s][0] = *(const float4*)(pA);
                *(float4*)&stA[s][4] = *(const float4*)(pA + 4);
                *(float4*)&stB[s][0] = *(const float4*)(pB);
                *(float4*)&stB[s][4] = *(const float4*)(pB + 4);
            }
        }

        #pragma unroll
        for (int ks = 0; ks < 2; ks++) {
            const int chi = ks * 2 + hb;

            uint32_t afr[4][4];
            #pragma unroll
            for (int mi = 0; mi < 4; mi++)
                LDSM_X4(afr[mi][0], afr[mi][1], afr[mi][2], afr[mi][3],
                        sw_addr(Ab, wm * 64 + mi * 16 + rin, chi));

            uint32_t bh[2][4];
            #pragma unroll
            for (int pi = 0; pi < 2; pi++)
                LDSM_X4(bh[pi][0], bh[pi][1], bh[pi][2], bh[pi][3],
                        sw_addr(Bb, wn * 32 + pi * 16 + rin, chi));

            #pragma unroll
            for (int mi = 0; mi < 4; mi++)
                #pragma unroll
                for (int ni = 0; ni < 4; ni++)
                    MMA_BF16(acc[mi][ni], afr[mi],
                             bh[ni >> 1][ni & 1], bh[ni >> 1][(ni & 1) + 2]);

            uint32_t bl[2][4];
            #pragma unroll
            for (int pi = 0; pi < 2; pi++)
                LDSM_X4(bl[pi][0], bl[pi][1], bl[pi][2], bl[pi][3],
                        sw_addr(Bb, wn * 32 + pi * 16 + rin, chi + 4));
            #pragma unroll
            for (int mi = 0; mi < 4; mi++)
                #pragma unroll
                for (int ni = 0; ni < 4; ni++)
                    MMA_BF16(acc[mi][ni], afr[mi],
                             bl[ni >> 1][ni & 1], bl[ni >> 1][(ni & 1) + 2]);

            #pragma unroll
            for (int mi = 0; mi < 4; mi++)
                LDSM_X4(afr[mi][0], afr[mi][1], afr[mi][2], afr[mi][3],
                        sw_addr(Ab, wm * 64 + mi * 16 + rin, chi + 4));
            #pragma unroll
            for (int mi = 0; mi < 4; mi++)
                #pragma unroll
                for (int ni = 0; ni < 4; ni++)
                    MMA_BF16(acc[mi][ni], afr[mi],
                             bh[ni >> 1][ni & 1], bh[ni >> 1][(ni & 1) + 2]);
        }
    }

    const int rbase = bm * 128 + wm * 64;
    const int cbase = bn * 128 + wn * 32;
    float bb[4][2];
    #pragma unroll
    for (int ni = 0; ni < 4; ni++) {
        int c0 = cbase + ni * 8 + (lane & 3) * 2;
        bb[ni][0] = bias[c0];
        bb[ni][1] = bias[c0 + 1];
    }

    #pragma unroll
    for (int mi = 0; mi < 4; mi++) {
        #pragma unroll
        for (int ni = 0; ni < 4; ni++) {
            int r0 = rbase + mi * 16 + (lane >> 2);
            int c0 = cbase + ni * 8 + (lane & 3) * 2;
            float o0 = acc[mi][ni][0] + bb[ni][0];
            float o1 = acc[mi][ni][1] + bb[ni][1];
            float o2 = acc[mi][ni][2] + bb[ni][0];
            float o3 = acc[mi][ni][3] + bb[ni][1];
            if (MODE == 1) {
                float2 ra = *(const float2*)&R[(size_t)r0 * DIMD + c0];
                float2 rb = *(const float2*)&R[(size_t)(r0 + 8) * DIMD + c0];
                o0 = fmaxf(o0, 0.0f) + ra.x;
                o1 = fmaxf(o1, 0.0f) + ra.y;
                o2 = fmaxf(o2, 0.0f) + rb.x;
                o3 = fmaxf(o3, 0.0f) + rb.y;
            }
            *(float2*)&C[(size_t)r0 * DIMD + c0]       = make_float2(o0, o1);
            *(float2*)&C[(size_t)(r0 + 8) * DIMD + c0] = make_float2(o2, o3);
        }
    }
}

// ================================================================================
// Tensor-core flash attention per (b,h): Br=128 (CTA), Bc=64, d=64, 8 warps.
// No max subtraction (scores provably tiny -> exp can't overflow; softmax is
// shift-invariant so this is exact). O accumulates raw; divide by l at end.
// P stays in registers (S-accum -> bf16x2 A-frags). Residual uses fp32 Qp.
// ================================================================================
#define ATT_SMEM (16384 + 8192 + 8192)

__global__ void __launch_bounds__(256)
attn_mma(const float* __restrict__ Qp, const float* __restrict__ Kp,
         const float* __restrict__ Vp, float* __restrict__ Oh)
{
    extern __shared__ char smatt[];
    const uint32_t sb = smem_u32(smatt);
    const uint32_t Qs = sb;
    const uint32_t Ks = sb + 16384;
    const uint32_t Vt = sb + 24576;

    const int t    = threadIdx.x;
    const int w    = t >> 5;
    const int lane = t & 31;
    const int rin  = lane & 15;
    const int hb   = lane >> 4;
    const int bh   = blockIdx.y;
    const int b    = bh >> 4;
    const int h    = bh & 15;
    const int n0   = blockIdx.x * 128;

    const size_t base = (size_t)b * SEQ * DIMD + (size_t)h * HD;

    // ---- stage Q tile: 128 rows x 64 d, fp32 -> bf16 swizzled ----
    {
        const int r  = t >> 1;
        const int cb = (t & 1) * 32;
        const float* src = Qp + base + (size_t)(n0 + r) * DIMD + cb;
        #pragma unroll
        for (int g = 0; g < 2; g++) {
            float4 f0 = *(const float4*)(src + g * 16);
            float4 f1 = *(const float4*)(src + g * 16 + 4);
            float4 f2 = *(const float4*)(src + g * 16 + 8);
            float4 f3 = *(const float4*)(src + g * 16 + 12);
            int ci = (t & 1) * 4 + g * 2;
            stb16(sw_addr(Qs, r, ci),     f0, f1);
            stb16(sw_addr(Qs, r, ci + 1), f2, f3);
        }
    }
    __syncthreads();

    // ---- load Q fragments once (warp owns rows w*16 .. w*16+16) ----
    uint32_t qf[4][4];
    #pragma unroll
    for (int ks = 0; ks < 4; ks++)
        LDSM_X4(qf[ks][0], qf[ks][1], qf[ks][2], qf[ks][3],
                sw_addr(Qs, w * 16 + rin, 2 * ks + hb));

    float oacc[8][4];
    #pragma unroll
    for (int j = 0; j < 8; j++)
        #pragma unroll
        for (int q = 0; q < 4; q++) oacc[j][q] = 0.0f;
    float l0 = 0.0f, l1 = 0.0f;

    for (int m0 = 0; m0 < SEQ; m0 += 64) {
        __syncthreads();   // previous iteration's reads done before restage

        // ---- stage K chunk: 64 keys x 64 d (k-major bf16 swizzled) ----
        {
            const int r  = t >> 2;
            const int cb = (t & 3) * 16;
            const float* src = Kp + base + (size_t)(m0 + r) * DIMD + cb;
            float4 f0 = *(const float4*)(src);
            float4 f1 = *(const float4*)(src + 4);
            float4 f2 = *(const float4*)(src + 8);
            float4 f3 = *(const float4*)(src + 12);
            int ci = (t & 3) * 2;
            stb16(sw_addr(Ks, r, ci),     f0, f1);
            stb16(sw_addr(Ks, r, ci + 1), f2, f3);
        }
        // ---- stage V chunk transposed: Vt[d=64 rows][key=64 cols] ----
        {
            const int kp = t & 31;     // key pair (2kp, 2kp+1)
            const int dg = t >> 5;     // d group: rows dg*8 .. +8
            const float* v0p = Vp + base + (size_t)(m0 + 2 * kp) * DIMD + dg * 8;
            const float* v1p = v0p + DIMD;
            float4 a0 = *(const float4*)(v0p);
            float4 a1 = *(const float4*)(v0p + 4);
            float4 b0 = *(const float4*)(v1p);
            float4 b1 = *(const float4*)(v1p + 4);
            float va[8] = {a0.x, a0.y, a0.z, a0.w, a1.x, a1.y, a1.z, a1.w};
            float vb[8] = {b0.x, b0.y, b0.z, b0.w, b1.x, b1.y, b1.z, b1.w};
            #pragma unroll
            for (int i = 0; i < 8; i++) {
                int d = dg * 8 + i;
                uint32_t pv = pkbf(va[i], vb[i]);
                uint32_t addr = Vt + (uint32_t)(d * 128)
                              + (uint32_t)((((kp >> 2) ^ (d & 7)) & 7) << 4)
                              + (uint32_t)((kp & 3) * 4);
                asm volatile("st.shared.b32 [%0], %1;" :: "r"(addr), "r"(pv));
            }
        }
        __syncthreads();

        // ---- S = Q K^T : warp computes 16 x 64 ----
        float sacc[8][4];
        #pragma unroll
        for (int j = 0; j < 8; j++)
            #pragma unroll
            for (int q = 0; q < 4; q++) sacc[j][q] = 0.0f;

        #pragma unroll
        for (int ks = 0; ks < 4; ks++) {
            uint32_t kb[4][4];
            #pragma unroll
            for (int pi = 0; pi < 4; pi++)
                LDSM_X4(kb[pi][0], kb[pi][1], kb[pi][2], kb[pi][3],
                        sw_addr(Ks, pi * 16 + rin, 2 * ks + hb));
            #pragma unroll
            for (int pi = 0; pi < 4; pi++) {
                MMA_BF16(sacc[2 * pi],     qf[ks], kb[pi][0], kb[pi][2]);
                MMA_BF16(sacc[2 * pi + 1], qf[ks], kb[pi][1], kb[pi][3]);
            }
        }

        // ---- p = exp(s/32); accumulate l; pack P -> bf16 A-frags ----
        uint32_t pf[8][2];
        #pragma unroll
        for (int j = 0; j < 8; j++) {
            float p0 = __expf(sacc[j][0] * 0.03125f);
            float p1 = __expf(sacc[j][1] * 0.03125f);
            float p2 = __expf(sacc[j][2] * 0.03125f);
            float p3 = __expf(sacc[j][3] * 0.03125f);
            l0 += p0 + p1;
            l1 += p2 + p3;
            pf[j][0] = pkbf(p0, p1);
            pf[j][1] = pkbf(p2, p3);
        }

        // ---- O += P @ V : warp computes 16 x 64 ----
        #pragma unroll
        for (int ks = 0; ks < 4; ks++) {
            uint32_t pa[4] = {pf[2 * ks][0], pf[2 * ks][1],
                              pf[2 * ks + 1][0], pf[2 * ks + 1][1]};
            uint32_t vb[4][4];
            #pragma unroll
            for (int pi = 0; pi < 4; pi++)
                LDSM_X4(vb[pi][0], vb[pi][1], vb[pi][2], vb[pi][3],
                        sw_addr(Vt, pi * 16 + rin, 2 * ks + hb));
            #pragma unroll
            for (int pi = 0; pi < 4; pi++) {
                MMA_BF16(oacc[2 * pi],     pa, vb[pi][0], vb[pi][2]);
                MMA_BF16(oacc[2 * pi + 1], pa, vb[pi][1], vb[pi][3]);
            }
        }
    }

    // ---- finalize: quad-reduce l, O = acc/l + Qp (fp32 residual) ----
    l0 += __shfl_xor_sync(0xffffffffu, l0, 1);
    l0 += __shfl_xor_sync(0xffffffffu, l0, 2);
    l1 += __shfl_xor_sync(0xffffffffu, l1, 1);
    l1 += __shfl_xor_sync(0xffffffffu, l1, 2);
    const float inv0 = 1.0f / l0;
    const float inv1 = 1.0f / l1;

    const int r0 = n0 + w * 16 + (lane >> 2);
    const int r1 = r0 + 8;
    #pragma unroll
    for (int j = 0; j < 8; j++) {
        const int col = j * 8 + (lane & 3) * 2;
        float2 q0 = *(const float2*)&Qp[base + (size_t)r0 * DIMD + col];
        float2 q1 = *(const float2*)&Qp[base + (size_t)r1 * DIMD + col];
        float2 o0 = make_float2(oacc[j][0] * inv0 + q0.x,
                                oacc[j][1] * inv0 + q0.y);
        float2 o1 = make_float2(oacc[j][2] * inv1 + q1.x,
                                oacc[j][3] * inv1 + q1.y);
        *(float2*)&Oh[base + (size_t)r0 * DIMD + col] = o0;
        *(float2*)&Oh[base + (size_t)r1 * DIMD + col] = o1;
    }
}

// ================================================================================
extern "C" void kernel_launch(void* const* d_in, const int* in_sizes, int n_in,
                              void* d_out, int out_size)
{
    const float* Q  = (const float*)d_in[0];
    const float* K  = (const float*)d_in[1];
    const float* Wq = (const float*)d_in[2];
    const float* bq = (const float*)d_in[3];
    const float* Wk = (const float*)d_in[4];
    const float* bk = (const float*)d_in[5];
    const float* Wv = (const float*)d_in[6];
    const float* bv = (const float*)d_in[7];
    const float* Wo = (const float*)d_in[8];
    const float* bo = (const float*)d_in[9];
    float* out = (float*)d_out;

    float *Qp, *Kp, *Vp, *Oh;
    cudaGetSymbolAddress((void**)&Qp, g_Qp);
    cudaGetSymbolAddress((void**)&Kp, g_Kp);
    cudaGetSymbolAddress((void**)&Vp, g_Vp);
    cudaGetSymbolAddress((void**)&Oh, g_Oh);

    cudaFuncSetAttribute(attn_mma,
                         cudaFuncAttributeMaxDynamicSharedMemorySize, ATT_SMEM);
    cudaFuncSetAttribute(gemm_mma<0>,
                         cudaFuncAttributeMaxDynamicSharedMemorySize, GEMM_SMEM);
    cudaFuncSetAttribute(gemm_mma<1>,
                         cudaFuncAttributeMaxDynamicSharedMemorySize, GEMM_SMEM);

    dim3 gg(8, 64);
    gemm_mma<0><<<gg, 256, GEMM_SMEM>>>(Q, Wq, bq, nullptr, Qp);
    gemm_mma<0><<<gg, 256, GEMM_SMEM>>>(K, Wk, bk, nullptr, Kp);
    gemm_mma<0><<<gg, 256, GEMM_SMEM>>>(K, Wv, bv, nullptr, Vp);
    attn_mma<<<dim3(16, 64), 256, ATT_SMEM>>>(Qp, Kp, Vp, Oh);
    gemm_mma<1><<<gg, 256, GEMM_SMEM>>>(Oh, Wo, bo, Oh, out);
}

// round 8
// speedup vs baseline: 4.4997x; 1.6016x over previous
#include <cuda_runtime.h>
#include <cuda_fp16.h>
#include <cstdint>
#include <cstddef>

#define DIMD   1024
#define TT     8192     // B*N = B*M rows
#define HD     64       // head dim
#define SEQ    2048

// ---------------- scratch ----------------
__device__ float g_Qp[TT * DIMD];
__device__ float g_Kp[TT * DIMD];
__device__ float g_Vp[TT * DIMD];
__device__ float g_Oh[TT * DIMD];

// =========================== helpers =================================
__device__ __forceinline__ uint32_t smem_u32(const void* p) {
    uint32_t a;
    asm("{ .reg .u64 t; cvta.to.shared.u64 t, %1; cvt.u32.u64 %0, t; }"
        : "=r"(a) : "l"(p));
    return a;
}

// ---------------- tensor-core (legacy mma.sync, fp16) helpers -------------------
#define LDSM_X4(R0, R1, R2, R3, addr) \
    asm volatile("ldmatrix.sync.aligned.m8n8.x4.shared.b16 {%0,%1,%2,%3}, [%4];" \
                 : "=r"(R0), "=r"(R1), "=r"(R2), "=r"(R3) : "r"(addr))

#define MMA_F16(c, a, b0, b1) \
    asm volatile("mma.sync.aligned.m16n8k16.row.col.f32.f16.f16.f32 " \
                 "{%0,%1,%2,%3}, {%4,%5,%6,%7}, {%8,%9}, {%0,%1,%2,%3};" \
                 : "+f"((c)[0]), "+f"((c)[1]), "+f"((c)[2]), "+f"((c)[3]) \
                 : "r"((a)[0]), "r"((a)[1]), "r"((a)[2]), "r"((a)[3]), \
                   "r"(b0), "r"(b1))

// pack two fp32 -> f16x2 (lo = element 0, hi = element 1)
__device__ __forceinline__ uint32_t pkhf(float lo, float hi) {
    uint32_t d;
    asm("cvt.rn.f16x2.f32 %0, %1, %2;" : "=r"(d) : "f"(hi), "f"(lo));
    return d;
}

// 8 floats -> 4 packed f16x2
__device__ __forceinline__ void cvt8h(const float* f, uint32_t* o) {
    #pragma unroll
    for (int i = 0; i < 4; i++) o[i] = pkhf(f[2 * i], f[2 * i + 1]);
}

// swizzled smem address: 128B rows, 8 chunks of 16B, chunk c XOR (r&7)
__device__ __forceinline__ uint32_t sw_addr(uint32_t base, int r, int c) {
    return base + (uint32_t)(r * 128) + (uint32_t)(((c ^ (r & 7)) & 7) << 4);
}

// store 8 fp16 (one 16B chunk) from two float4
__device__ __forceinline__ void sth16(uint32_t a, float4 f0, float4 f1) {
    uint32_t r0 = pkhf(f0.x, f0.y), r1 = pkhf(f0.z, f0.w);
    uint32_t r2 = pkhf(f1.x, f1.y), r3 = pkhf(f1.z, f1.w);
    asm volatile("st.shared.v4.b32 [%0], {%1,%2,%3,%4};"
                 :: "r"(a), "r"(r0), "r"(r1), "r"(r2), "r"(r3));
}

// ================================================================================
// fp16 single-pass tensor-core GEMM:
//   C[8192,1024] = X[8192,1024] @ W[1024,1024]^T (+bias) (+MODE1: relu+residual)
// 128x128 tile, BK=32, 256 threads (8 warps, 2m x 4n), warp tile 64x32.
// ================================================================================
#define GEMM_SMEM (2 * 32768)

template <int MODE>
__global__ void __launch_bounds__(256)
gemm_mma(const float* __restrict__ X, const float* __restrict__ W,
         const float* __restrict__ bias, const float* __restrict__ R,
         float* __restrict__ C)
{
    extern __shared__ char sm[];
    const uint32_t sb = smem_u32(sm);

    const int t    = threadIdx.x;
    const int w    = t >> 5;
    const int lane = t & 31;
    const int wm   = w >> 2;
    const int wn   = w & 3;
    const int bn   = blockIdx.x;
    const int bm   = blockIdx.y;

    float acc[4][4][4];
    #pragma unroll
    for (int mi = 0; mi < 4; mi++)
        #pragma unroll
        for (int ni = 0; ni < 4; ni++)
            #pragma unroll
            for (int q = 0; q < 4; q++) acc[mi][ni][q] = 0.0f;

    float stA[2][8], stB[2][8];

    #pragma unroll
    for (int s = 0; s < 2; s++) {
        int idx = t + 256 * s;
        int r = idx >> 2, seg = idx & 3;
        const float* pA = X + (size_t)(bm * 128 + r) * DIMD + seg * 8;
        const float* pB = W + (size_t)(bn * 128 + r) * DIMD + seg * 8;
        *(float4*)&stA[s][0] = *(const float4*)(pA);
        *(float4*)&stA[s][4] = *(const float4*)(pA + 4);
        *(float4*)&stB[s][0] = *(const float4*)(pB);
        *(float4*)&stB[s][4] = *(const float4*)(pB + 4);
    }

    const int rin = lane & 15;
    const int hb  = lane >> 4;

    for (int ch = 0; ch < 32; ch++) {
        const uint32_t Ab = sb + (uint32_t)(ch & 1) * 32768u;
        const uint32_t Bb = Ab + 16384u;

        // store staged chunk (fp16, chunks 0-3 of each 128B row)
        #pragma unroll
        for (int s = 0; s < 2; s++) {
            int idx = t + 256 * s;
            int r = idx >> 2, seg = idx & 3;
            uint32_t h[4];
            cvt8h(stA[s], h);
            asm volatile("st.shared.v4.b32 [%0], {%1,%2,%3,%4};"
                         :: "r"(sw_addr(Ab, r, seg)),
                            "r"(h[0]), "r"(h[1]), "r"(h[2]), "r"(h[3]));
            cvt8h(stB[s], h);
            asm volatile("st.shared.v4.b32 [%0], {%1,%2,%3,%4};"
                         :: "r"(sw_addr(Bb, r, seg)),
                            "r"(h[0]), "r"(h[1]), "r"(h[2]), "r"(h[3]));
        }
        __syncthreads();

        if (ch + 1 < 32) {
            const int k0 = (ch + 1) * 32;
            #pragma unroll
            for (int s = 0; s < 2; s++) {
                int idx = t + 256 * s;
                int r = idx >> 2, seg = idx & 3;
                const float* pA = X + (size_t)(bm * 128 + r) * DIMD + k0 + seg * 8;
                const float* pB = W + (size_t)(bn * 128 + r) * DIMD + k0 + seg * 8;
                *(float4*)&stA[s][0] = *(const float4*)(pA);
                *(float4*)&stA[s][4] = *(const float4*)(pA + 4);
                *(float4*)&stB[s][0] = *(const float4*)(pB);
                *(float4*)&stB[s][4] = *(const float4*)(pB + 4);
            }
        }

        // single-pass MMA over this chunk: 2 k16-steps
        #pragma unroll
        for (int ks = 0; ks < 2; ks++) {
            const int chi = ks * 2 + hb;

            uint32_t afr[4][4];
            #pragma unroll
            for (int mi = 0; mi < 4; mi++)
                LDSM_X4(afr[mi][0], afr[mi][1], afr[mi][2], afr[mi][3],
                        sw_addr(Ab, wm * 64 + mi * 16 + rin, chi));

            uint32_t bh[2][4];
            #pragma unroll
            for (int pi = 0; pi < 2; pi++)
                LDSM_X4(bh[pi][0], bh[pi][1], bh[pi][2], bh[pi][3],
                        sw_addr(Bb, wn * 32 + pi * 16 + rin, chi));

            #pragma unroll
            for (int mi = 0; mi < 4; mi++)
                #pragma unroll
                for (int ni = 0; ni < 4; ni++)
                    MMA_F16(acc[mi][ni], afr[mi],
                            bh[ni >> 1][ni & 1], bh[ni >> 1][(ni & 1) + 2]);
        }
        __syncthreads();
    }

    const int rbase = bm * 128 + wm * 64;
    const int cbase = bn * 128 + wn * 3 * 0 + wn * 32;
    float bb[4][2];
    #pragma unroll
    for (int ni = 0; ni < 4; ni++) {
        int c0 = cbase + ni * 8 + (lane & 3) * 2;
        bb[ni][0] = bias[c0];
        bb[ni][1] = bias[c0 + 1];
    }

    #pragma unroll
    for (int mi = 0; mi < 4; mi++) {
        #pragma unroll
        for (int ni = 0; ni < 4; ni++) {
            int r0 = rbase + mi * 16 + (lane >> 2);
            int c0 = cbase + ni * 8 + (lane & 3) * 2;
            float o0 = acc[mi][ni][0] + bb[ni][0];
            float o1 = acc[mi][ni][1] + bb[ni][1];
            float o2 = acc[mi][ni][2] + bb[ni][0];
            float o3 = acc[mi][ni][3] + bb[ni][1];
            if (MODE == 1) {
                float2 ra = *(const float2*)&R[(size_t)r0 * DIMD + c0];
                float2 rb = *(const float2*)&R[(size_t)(r0 + 8) * DIMD + c0];
                o0 = fmaxf(o0, 0.0f) + ra.x;
                o1 = fmaxf(o1, 0.0f) + ra.y;
                o2 = fmaxf(o2, 0.0f) + rb.x;
                o3 = fmaxf(o3, 0.0f) + rb.y;
            }
            *(float2*)&C[(size_t)r0 * DIMD + c0]       = make_float2(o0, o1);
            *(float2*)&C[(size_t)(r0 + 8) * DIMD + c0] = make_float2(o2, o3);
        }
    }
}

// ================================================================================
// Tensor-core flash attention per (b,h): Br=128 (CTA), Bc=64, d=64, 8 warps.
// fp16 operands, fp32 accum. No max subtraction (scores provably tiny).
// ================================================================================
#define ATT_SMEM (16384 + 8192 + 8192)

__global__ void __launch_bounds__(256)
attn_mma(const float* __restrict__ Qp, const float* __restrict__ Kp,
         const float* __restrict__ Vp, float* __restrict__ Oh)
{
    extern __shared__ char smatt[];
    const uint32_t sb = smem_u32(smatt);
    const uint32_t Qs = sb;
    const uint32_t Ks = sb + 16384;
    const uint32_t Vt = sb + 24576;

    const int t    = threadIdx.x;
    const int w    = t >> 5;
    const int lane = t & 31;
    const int rin  = lane & 15;
    const int hb   = lane >> 4;
    const int bh   = blockIdx.y;
    const int b    = bh >> 4;
    const int h    = bh & 15;
    const int n0   = blockIdx.x * 128;

    const size_t base = (size_t)b * SEQ * DIMD + (size_t)h * HD;

    // ---- stage Q tile: 128 rows x 64 d, fp32 -> fp16 swizzled ----
    {
        const int r  = t >> 1;
        const int cb = (t & 1) * 32;
        const float* src = Qp + base + (size_t)(n0 + r) * DIMD + cb;
        #pragma unroll
        for (int g = 0; g < 2; g++) {
            float4 f0 = *(const float4*)(src + g * 16);
            float4 f1 = *(const float4*)(src + g * 16 + 4);
            float4 f2 = *(const float4*)(src + g * 16 + 8);
            float4 f3 = *(const float4*)(src + g * 16 + 12);
            int ci = (t & 1) * 4 + g * 2;
            sth16(sw_addr(Qs, r, ci),     f0, f1);
            sth16(sw_addr(Qs, r, ci + 1), f2, f3);
        }
    }
    __syncthreads();

    // ---- load Q fragments once ----
    uint32_t qf[4][4];
    #pragma unroll
    for (int ks = 0; ks < 4; ks++)
        LDSM_X4(qf[ks][0], qf[ks][1], qf[ks][2], qf[ks][3],
                sw_addr(Qs, w * 16 + rin, 2 * ks + hb));

    float oacc[8][4];
    #pragma unroll
    for (int j = 0; j < 8; j++)
        #pragma unroll
        for (int q = 0; q < 4; q++) oacc[j][q] = 0.0f;
    float l0 = 0.0f, l1 = 0.0f;

    for (int m0 = 0; m0 < SEQ; m0 += 64) {
        __syncthreads();

        // ---- stage K chunk: 64 keys x 64 d ----
        {
            const int r  = t >> 2;
            const int cb = (t & 3) * 16;
            const float* src = Kp + base + (size_t)(m0 + r) * DIMD + cb;
            float4 f0 = *(const float4*)(src);
            float4 f1 = *(const float4*)(src + 4);
            float4 f2 = *(const float4*)(src + 8);
            float4 f3 = *(const float4*)(src + 12);
            int ci = (t & 3) * 2;
            sth16(sw_addr(Ks, r, ci),     f0, f1);
            sth16(sw_addr(Ks, r, ci + 1), f2, f3);
        }
        // ---- stage V chunk transposed: Vt[d=64 rows][key=64 cols] ----
        {
            const int kp = t & 31;
            const int dg = t >> 5;
            const float* v0p = Vp + base + (size_t)(m0 + 2 * kp) * DIMD + dg * 8;
            const float* v1p = v0p + DIMD;
            float4 a0 = *(const float4*)(v0p);
            float4 a1 = *(const float4*)(v0p + 4);
            float4 b0 = *(const float4*)(v1p);
            float4 b1 = *(const float4*)(v1p + 4);
            float va[8] = {a0.x, a0.y, a0.z, a0.w, a1.x, a1.y, a1.z, a1.w};
            float vb[8] = {b0.x, b0.y, b0.z, b0.w, b1.x, b1.y, b1.z, b1.w};
            #pragma unroll
            for (int i = 0; i < 8; i++) {
                int d = dg * 8 + i;
                uint32_t pv = pkhf(va[i], vb[i]);
                uint32_t addr = Vt + (uint32_t)(d * 128)
                              + (uint32_t)((((kp >> 2) ^ (d & 7)) & 7) << 4)
                              + (uint32_t)((kp & 3) * 4);
                asm volatile("st.shared.b32 [%0], %1;" :: "r"(addr), "r"(pv));
            }
        }
        __syncthreads();

        // ---- S = Q K^T ----
        float sacc[8][4];
        #pragma unroll
        for (int j = 0; j < 8; j++)
            #pragma unroll
            for (int q = 0; q < 4; q++) sacc[j][q] = 0.0f;

        #pragma unroll
        for (int ks = 0; ks < 4; ks++) {
            uint32_t kb[4][4];
            #pragma unroll
            for (int pi = 0; pi < 4; pi++)
                LDSM_X4(kb[pi][0], kb[pi][1], kb[pi][2], kb[pi][3],
                        sw_addr(Ks, pi * 16 + rin, 2 * ks + hb));
            #pragma unroll
            for (int pi = 0; pi < 4; pi++) {
                MMA_F16(sacc[2 * pi],     qf[ks], kb[pi][0], kb[pi][2]);
                MMA_F16(sacc[2 * pi + 1], qf[ks], kb[pi][1], kb[pi][3]);
            }
        }

        // ---- p = exp(s/32); accumulate l; pack P ----
        uint32_t pf[8][2];
        #pragma unroll
        for (int j = 0; j < 8; j++) {
            float p0 = __expf(sacc[j][0] * 0.03125f);
            float p1 = __expf(sacc[j][1] * 0.03125f);
            float p2 = __expf(sacc[j][2] * 0.03125f);
            float p3 = __expf(sacc[j][3] * 0.03125f);
            l0 += p0 + p1;
            l1 += p2 + p3;
            pf[j][0] = pkhf(p0, p1);
            pf[j][1] = pkhf(p2, p3);
        }

        // ---- O += P @ V ----
        #pragma unroll
        for (int ks = 0; ks < 4; ks++) {
            uint32_t pa[4] = {pf[2 * ks][0], pf[2 * ks][1],
                              pf[2 * ks + 1][0], pf[2 * ks + 1][1]};
            uint32_t vb[4][4];
            #pragma unroll
            for (int pi = 0; pi < 4; pi++)
                LDSM_X4(vb[pi][0], vb[pi][1], vb[pi][2], vb[pi][3],
                        sw_addr(Vt, pi * 16 + rin, 2 * ks + hb));
            #pragma unroll
            for (int pi = 0; pi < 4; pi++) {
                MMA_F16(oacc[2 * pi],     pa, vb[pi][0], vb[pi][2]);
                MMA_F16(oacc[2 * pi + 1], pa, vb[pi][1], vb[pi][3]);
            }
        }
    }

    // ---- finalize ----
    l0 += __shfl_xor_sync(0xffffffffu, l0, 1);
    l0 += __shfl_xor_sync(0xffffffffu, l0, 2);
    l1 += __shfl_xor_sync(0xffffffffu, l1, 1);
    l1 += __shfl_xor_sync(0xffffffffu, l1, 2);
    const float inv0 = 1.0f / l0;
    const float inv1 = 1.0f / l1;

    const int r0 = n0 + w * 16 + (lane >> 2);
    const int r1 = r0 + 8;
    #pragma unroll
    for (int j = 0; j < 8; j++) {
        const int col = j * 8 + (lane & 3) * 2;
        float2 q0 = *(const float2*)&Qp[base + (size_t)r0 * DIMD + col];
        float2 q1 = *(const float2*)&Qp[base + (size_t)r1 * DIMD + col];
        float2 o0 = make_float2(oacc[j][0] * inv0 + q0.x,
                                oacc[j][1] * inv0 + q0.y);
        float2 o1 = make_float2(oacc[j][2] * inv1 + q1.x,
                                oacc[j][3] * inv1 + q1.y);
        *(float2*)&Oh[base + (size_t)r0 * DIMD + col] = o0;
        *(float2*)&Oh[base + (size_t)r1 * DIMD + col] = o1;
    }
}

// ================================================================================
extern "C" void kernel_launch(void* const* d_in, const int* in_sizes, int n_in,
                              void* d_out, int out_size)
{
    const float* Q  = (const float*)d_in[0];
    const float* K  = (const float*)d_in[1];
    const float* Wq = (const float*)d_in[2];
    const float* bq = (const float*)d_in[3];
    const float* Wk = (const float*)d_in[4];
    const float* bk = (const float*)d_in[5];
    const float* Wv = (const float*)d_in[6];
    const float* bv = (const float*)d_in[7];
    const float* Wo = (const float*)d_in[8];
    const float* bo = (const float*)d_in[9];
    float* out = (float*)d_out;

    float *Qp, *Kp, *Vp, *Oh;
    cudaGetSymbolAddress((void**)&Qp, g_Qp);
    cudaGetSymbolAddress((void**)&Kp, g_Kp);
    cudaGetSymbolAddress((void**)&Vp, g_Vp);
    cudaGetSymbolAddress((void**)&Oh, g_Oh);

    cudaFuncSetAttribute(attn_mma,
                         cudaFuncAttributeMaxDynamicSharedMemorySize, ATT_SMEM);
    cudaFuncSetAttribute(gemm_mma<0>,
                         cudaFuncAttributeMaxDynamicSharedMemorySize, GEMM_SMEM);
    cudaFuncSetAttribute(gemm_mma<1>,
                         cudaFuncAttributeMaxDynamicSharedMemorySize, GEMM_SMEM);

    dim3 gg(8, 64);
    gemm_mma<0><<<gg, 256, GEMM_SMEM>>>(Q, Wq, bq, nullptr, Qp);
    gemm_mma<0><<<gg, 256, GEMM_SMEM>>>(K, Wk, bk, nullptr, Kp);
    gemm_mma<0><<<gg, 256, GEMM_SMEM>>>(K, Wv, bv, nullptr, Vp);
    attn_mma<<<dim3(16, 64), 256, ATT_SMEM>>>(Qp, Kp, Vp, Oh);
    gemm_mma<1><<<gg, 256, GEMM_SMEM>>>(Oh, Wo, bo, Oh, out);
}

// round 9
// speedup vs baseline: 5.9319x; 1.3183x over previous
#include <cuda_runtime.h>
#include <cuda_fp16.h>
#include <cstdint>
#include <cstddef>

#define DIMD   1024
#define TT     8192     // B*N = B*M rows
#define HD     64       // head dim
#define SEQ    2048

// ---------------- scratch ----------------
__device__ float  g_Qp [TT * DIMD];   // fp32 Q projection (residual)
__device__ float  g_Oh [TT * DIMD];   // fp32 attention out (residual for final gemm)
__device__ __half g_Qh [TT * DIMD];
__device__ __half g_Kh [TT * DIMD];
__device__ __half g_Vh [TT * DIMD];
__device__ __half g_OhH[TT * DIMD];

// =========================== helpers =================================
__device__ __forceinline__ uint32_t smem_u32(const void* p) {
    uint32_t a;
    asm("{ .reg .u64 t; cvta.to.shared.u64 t, %1; cvt.u32.u64 %0, t; }"
        : "=r"(a) : "l"(p));
    return a;
}

#define LDSM_X4(R0, R1, R2, R3, addr) \
    asm volatile("ldmatrix.sync.aligned.m8n8.x4.shared.b16 {%0,%1,%2,%3}, [%4];" \
                 : "=r"(R0), "=r"(R1), "=r"(R2), "=r"(R3) : "r"(addr))

#define LDSM_X4_T(R0, R1, R2, R3, addr) \
    asm volatile("ldmatrix.sync.aligned.m8n8.x4.trans.shared.b16 {%0,%1,%2,%3}, [%4];" \
                 : "=r"(R0), "=r"(R1), "=r"(R2), "=r"(R3) : "r"(addr))

#define MMA_F16(c, a, b0, b1) \
    asm volatile("mma.sync.aligned.m16n8k16.row.col.f32.f16.f16.f32 " \
                 "{%0,%1,%2,%3}, {%4,%5,%6,%7}, {%8,%9}, {%0,%1,%2,%3};" \
                 : "+f"((c)[0]), "+f"((c)[1]), "+f"((c)[2]), "+f"((c)[3]) \
                 : "r"((a)[0]), "r"((a)[1]), "r"((a)[2]), "r"((a)[3]), \
                   "r"(b0), "r"(b1))

__device__ __forceinline__ uint32_t pkhf(float lo, float hi) {
    uint32_t d;
    asm("cvt.rn.f16x2.f32 %0, %1, %2;" : "=r"(d) : "f"(hi), "f"(lo));
    return d;
}
__device__ __forceinline__ void cvt8h(const float* f, uint32_t* o) {
    #pragma unroll
    for (int i = 0; i < 4; i++) o[i] = pkhf(f[2 * i], f[2 * i + 1]);
}

// swizzled smem address: 128B rows, 8 chunks of 16B, chunk c XOR (r&7)
__device__ __forceinline__ uint32_t sw_addr(uint32_t base, int r, int c) {
    return base + (uint32_t)(r * 128) + (uint32_t)(((c ^ (r & 7)) & 7) << 4);
}

__device__ __forceinline__ void st16(uint32_t a, uint4 v) {
    asm volatile("st.shared.v4.b32 [%0], {%1,%2,%3,%4};"
                 :: "r"(a), "r"(v.x), "r"(v.y), "r"(v.z), "r"(v.w));
}

// ================================================================================
// Projection GEMM: C = X[8192,1024] @ W^T + bias -> fp16 CH (and fp32 C32 if W32)
// 128x128 tile, BK=32, 256 threads (8 warps, 2m x 4n), warp tile 64x32.
// ================================================================================
#define GEMM_SMEM (2 * 32768)

template <int W32>
__global__ void __launch_bounds__(256)
gemm_proj(const float* __restrict__ X, const float* __restrict__ W,
          const float* __restrict__ bias, float* __restrict__ C32,
          __half* __restrict__ CH)
{
    extern __shared__ char sm[];
    const uint32_t sb = smem_u32(sm);

    const int t    = threadIdx.x;
    const int w    = t >> 5;
    const int lane = t & 31;
    const int wm   = w >> 2;
    const int wn   = w & 3;
    const int bn   = blockIdx.x;
    const int bm   = blockIdx.y;

    float acc[4][4][4];
    #pragma unroll
    for (int mi = 0; mi < 4; mi++)
        #pragma unroll
        for (int ni = 0; ni < 4; ni++)
            #pragma unroll
            for (int q = 0; q < 4; q++) acc[mi][ni][q] = 0.0f;

    float stA[2][8], stB[2][8];
    #pragma unroll
    for (int s = 0; s < 2; s++) {
        int idx = t + 256 * s;
        int r = idx >> 2, seg = idx & 3;
        const float* pA = X + (size_t)(bm * 128 + r) * DIMD + seg * 8;
        const float* pB = W + (size_t)(bn * 128 + r) * DIMD + seg * 8;
        *(float4*)&stA[s][0] = *(const float4*)(pA);
        *(float4*)&stA[s][4] = *(const float4*)(pA + 4);
        *(float4*)&stB[s][0] = *(const float4*)(pB);
        *(float4*)&stB[s][4] = *(const float4*)(pB + 4);
    }

    const int rin = lane & 15;
    const int hb  = lane >> 4;

    for (int ch = 0; ch < 32; ch++) {
        const uint32_t Ab = sb + (uint32_t)(ch & 1) * 32768u;
        const uint32_t Bb = Ab + 16384u;

        #pragma unroll
        for (int s = 0; s < 2; s++) {
            int idx = t + 256 * s;
            int r = idx >> 2, seg = idx & 3;
            uint32_t h[4];
            cvt8h(stA[s], h);
            st16(sw_addr(Ab, r, seg), make_uint4(h[0], h[1], h[2], h[3]));
            cvt8h(stB[s], h);
            st16(sw_addr(Bb, r, seg), make_uint4(h[0], h[1], h[2], h[3]));
        }
        __syncthreads();

        if (ch + 1 < 32) {
            const int k0 = (ch + 1) * 32;
            #pragma unroll
            for (int s = 0; s < 2; s++) {
                int idx = t + 256 * s;
                int r = idx >> 2, seg = idx & 3;
                const float* pA = X + (size_t)(bm * 128 + r) * DIMD + k0 + seg * 8;
                const float* pB = W + (size_t)(bn * 128 + r) * DIMD + k0 + seg * 8;
                *(float4*)&stA[s][0] = *(const float4*)(pA);
                *(float4*)&stA[s][4] = *(const float4*)(pA + 4);
                *(float4*)&stB[s][0] = *(const float4*)(pB);
                *(float4*)&stB[s][4] = *(const float4*)(pB + 4);
            }
        }

        #pragma unroll
        for (int ks = 0; ks < 2; ks++) {
            const int chi = ks * 2 + hb;
            uint32_t afr[4][4];
            #pragma unroll
            for (int mi = 0; mi < 4; mi++)
                LDSM_X4(afr[mi][0], afr[mi][1], afr[mi][2], afr[mi][3],
                        sw_addr(Ab, wm * 64 + mi * 16 + rin, chi));
            uint32_t bh[2][4];
            #pragma unroll
            for (int pi = 0; pi < 2; pi++)
                LDSM_X4(bh[pi][0], bh[pi][1], bh[pi][2], bh[pi][3],
                        sw_addr(Bb, wn * 32 + pi * 16 + rin, chi));
            #pragma unroll
            for (int mi = 0; mi < 4; mi++)
                #pragma unroll
                for (int ni = 0; ni < 4; ni++)
                    MMA_F16(acc[mi][ni], afr[mi],
                            bh[ni >> 1][ni & 1], bh[ni >> 1][(ni & 1) + 2]);
        }
        __syncthreads();
    }

    const int rbase = bm * 128 + wm * 64;
    const int cbase = bn * 128 + wn * 32;
    float bb[4][2];
    #pragma unroll
    for (int ni = 0; ni < 4; ni++) {
        int c0 = cbase + ni * 8 + (lane & 3) * 2;
        bb[ni][0] = bias[c0];
        bb[ni][1] = bias[c0 + 1];
    }

    #pragma unroll
    for (int mi = 0; mi < 4; mi++) {
        #pragma unroll
        for (int ni = 0; ni < 4; ni++) {
            int r0 = rbase + mi * 16 + (lane >> 2);
            int c0 = cbase + ni * 8 + (lane & 3) * 2;
            float o0 = acc[mi][ni][0] + bb[ni][0];
            float o1 = acc[mi][ni][1] + bb[ni][1];
            float o2 = acc[mi][ni][2] + bb[ni][0];
            float o3 = acc[mi][ni][3] + bb[ni][1];
            *(uint32_t*)&CH[(size_t)r0 * DIMD + c0]       = pkhf(o0, o1);
            *(uint32_t*)&CH[(size_t)(r0 + 8) * DIMD + c0] = pkhf(o2, o3);
            if (W32) {
                *(float2*)&C32[(size_t)r0 * DIMD + c0]       = make_float2(o0, o1);
                *(float2*)&C32[(size_t)(r0 + 8) * DIMD + c0] = make_float2(o2, o3);
            }
        }
    }
}

// ================================================================================
// Output GEMM: out = R + relu(Xh @ W^T + bias), Xh fp16, R/out fp32.
// ================================================================================
__global__ void __launch_bounds__(256)
gemm_out(const __half* __restrict__ X, const float* __restrict__ W,
         const float* __restrict__ bias, const float* __restrict__ R,
         float* __restrict__ C)
{
    extern __shared__ char sm[];
    const uint32_t sb = smem_u32(sm);

    const int t    = threadIdx.x;
    const int w    = t >> 5;
    const int lane = t & 31;
    const int wm   = w >> 2;
    const int wn   = w & 3;
    const int bn   = blockIdx.x;
    const int bm   = blockIdx.y;

    float acc[4][4][4];
    #pragma unroll
    for (int mi = 0; mi < 4; mi++)
        #pragma unroll
        for (int ni = 0; ni < 4; ni++)
            #pragma unroll
            for (int q = 0; q < 4; q++) acc[mi][ni][q] = 0.0f;

    uint4 stA[2];
    float stB[2][8];
    #pragma unroll
    for (int s = 0; s < 2; s++) {
        int idx = t + 256 * s;
        int r = idx >> 2, seg = idx & 3;
        stA[s] = *(const uint4*)&X[(size_t)(bm * 128 + r) * DIMD + seg * 8];
        const float* pB = W + (size_t)(bn * 128 + r) * DIMD + seg * 8;
        *(float4*)&stB[s][0] = *(const float4*)(pB);
        *(float4*)&stB[s][4] = *(const float4*)(pB + 4);
    }

    const int rin = lane & 15;
    const int hb  = lane >> 4;

    for (int ch = 0; ch < 32; ch++) {
        const uint32_t Ab = sb + (uint32_t)(ch & 1) * 32768u;
        const uint32_t Bb = Ab + 16384u;

        #pragma unroll
        for (int s = 0; s < 2; s++) {
            int idx = t + 256 * s;
            int r = idx >> 2, seg = idx & 3;
            st16(sw_addr(Ab, r, seg), stA[s]);
            uint32_t h[4];
            cvt8h(stB[s], h);
            st16(sw_addr(Bb, r, seg), make_uint4(h[0], h[1], h[2], h[3]));
        }
        __syncthreads();

        if (ch + 1 < 32) {
            const int k0 = (ch + 1) * 32;
            #pragma unroll
            for (int s = 0; s < 2; s++) {
                int idx = t + 256 * s;
                int r = idx >> 2, seg = idx & 3;
                stA[s] = *(const uint4*)&X[(size_t)(bm * 128 + r) * DIMD + k0 + seg * 8];
                const float* pB = W + (size_t)(bn * 128 + r) * DIMD + k0 + seg * 8;
                *(float4*)&stB[s][0] = *(const float4*)(pB);
                *(float4*)&stB[s][4] = *(const float4*)(pB + 4);
            }
        }

        #pragma unroll
        for (int ks = 0; ks < 2; ks++) {
            const int chi = ks * 2 + hb;
            uint32_t afr[4][4];
            #pragma unroll
            for (int mi = 0; mi < 4; mi++)
                LDSM_X4(afr[mi][0], afr[mi][1], afr[mi][2], afr[mi][3],
                        sw_addr(Ab, wm * 64 + mi * 16 + rin, chi));
            uint32_t bh[2][4];
            #pragma unroll
            for (int pi = 0; pi < 2; pi++)
                LDSM_X4(bh[pi][0], bh[pi][1], bh[pi][2], bh[pi][3],
                        sw_addr(Bb, wn * 32 + pi * 16 + rin, chi));
            #pragma unroll
            for (int mi = 0; mi < 4; mi++)
                #pragma unroll
                for (int ni = 0; ni < 4; ni++)
                    MMA_F16(acc[mi][ni], afr[mi],
                            bh[ni >> 1][ni & 1], bh[ni >> 1][(ni & 1) + 2]);
        }
        __syncthreads();
    }

    const int rbase = bm * 128 + wm * 64;
    const int cbase = bn * 128 + wn * 32;
    float bb[4][2];
    #pragma unroll
    for (int ni = 0; ni < 4; ni++) {
        int c0 = cbase + ni * 8 + (lane & 3) * 2;
        bb[ni][0] = bias[c0];
        bb[ni][1] = bias[c0 + 1];
    }

    #pragma unroll
    for (int mi = 0; mi < 4; mi++) {
        #pragma unroll
        for (int ni = 0; ni < 4; ni++) {
            int r0 = rbase + mi * 16 + (lane >> 2);
            int c0 = cbase + ni * 8 + (lane & 3) * 2;
            float2 ra = *(const float2*)&R[(size_t)r0 * DIMD + c0];
            float2 rb = *(const float2*)&R[(size_t)(r0 + 8) * DIMD + c0];
            float o0 = fmaxf(acc[mi][ni][0] + bb[ni][0], 0.0f) + ra.x;
            float o1 = fmaxf(acc[mi][ni][1] + bb[ni][1], 0.0f) + ra.y;
            float o2 = fmaxf(acc[mi][ni][2] + bb[ni][0], 0.0f) + rb.x;
            float o3 = fmaxf(acc[mi][ni][3] + bb[ni][1], 0.0f) + rb.y;
            *(float2*)&C[(size_t)r0 * DIMD + c0]       = make_float2(o0, o1);
            *(float2*)&C[(size_t)(r0 + 8) * DIMD + c0] = make_float2(o2, o3);
        }
    }
}

// ================================================================================
// Tensor-core flash attention per (b,h): Br=128 (CTA), Bc=64, d=64, 8 warps.
// fp16 inputs (pre-converted), fp32 accum. No max subtraction (scores tiny).
// V fragments via ldmatrix.trans from row-major smem. K/V register prefetch.
// ================================================================================
#define ATT_SMEM (16384 + 8192 + 8192)

__global__ void __launch_bounds__(256, 2)
attn_mma(const __half* __restrict__ Qh, const __half* __restrict__ Kh,
         const __half* __restrict__ Vh, const float* __restrict__ Qp,
         float* __restrict__ Oh, __half* __restrict__ OhH)
{
    extern __shared__ char smatt[];
    const uint32_t sb = smem_u32(smatt);
    const uint32_t Qs = sb;
    const uint32_t Ks = sb + 16384;
    const uint32_t Vs = sb + 24576;

    const int t    = threadIdx.x;
    const int w    = t >> 5;
    const int lane = t & 31;
    const int rin  = lane & 15;
    const int hb   = lane >> 4;
    const int bh   = blockIdx.y;
    const int b    = bh >> 4;
    const int h    = bh & 15;
    const int n0   = blockIdx.x * 128;

    const size_t base = (size_t)b * SEQ * DIMD + (size_t)h * HD;

    // ---- stage Q tile: 128 rows x 64 d fp16, swizzled ----
    {
        const int r  = t >> 1;
        const int c0 = (t & 1) * 4;           // 4 chunks of 16B
        const __half* src = Qh + base + (size_t)(n0 + r) * DIMD + c0 * 8;
        #pragma unroll
        for (int g = 0; g < 4; g++)
            st16(sw_addr(Qs, r, c0 + g), *(const uint4*)(src + g * 8));
    }
    __syncthreads();

    // ---- load Q fragments once ----
    uint32_t qf[4][4];
    #pragma unroll
    for (int ks = 0; ks < 4; ks++)
        LDSM_X4(qf[ks][0], qf[ks][1], qf[ks][2], qf[ks][3],
                sw_addr(Qs, w * 16 + rin, 2 * ks + hb));

    float oacc[8][4];
    #pragma unroll
    for (int j = 0; j < 8; j++)
        #pragma unroll
        for (int q = 0; q < 4; q++) oacc[j][q] = 0.0f;
    float l0 = 0.0f, l1 = 0.0f;

    // prefetch chunk 0 (K and V, 32B each per thread)
    const int srow = t >> 2;        // 0..63
    const int sseg = t & 3;         // 16-half segment pair
    uint4 kpre[2], vpre[2];
    {
        const __half* kp = Kh + base + (size_t)srow * DIMD + sseg * 16;
        const __half* vp = Vh + base + (size_t)srow * DIMD + sseg * 16;
        kpre[0] = *(const uint4*)(kp);
        kpre[1] = *(const uint4*)(kp + 8);
        vpre[0] = *(const uint4*)(vp);
        vpre[1] = *(const uint4*)(vp + 8);
    }

    for (int m0 = 0; m0 < SEQ; m0 += 64) {
        // store staged K/V chunk
        st16(sw_addr(Ks, srow, sseg * 2),     kpre[0]);
        st16(sw_addr(Ks, srow, sseg * 2 + 1), kpre[1]);
        st16(sw_addr(Vs, srow, sseg * 2),     vpre[0]);
        st16(sw_addr(Vs, srow, sseg * 2 + 1), vpre[1]);
        __syncthreads();

        // prefetch next chunk
        if (m0 + 64 < SEQ) {
            const __half* kp = Kh + base + (size_t)(m0 + 64 + srow) * DIMD + sseg * 16;
            const __half* vp = Vh + base + (size_t)(m0 + 64 + srow) * DIMD + sseg * 16;
            kpre[0] = *(const uint4*)(kp);
            kpre[1] = *(const uint4*)(kp + 8);
            vpre[0] = *(const uint4*)(vp);
            vpre[1] = *(const uint4*)(vp + 8);
        }

        // ---- S = Q K^T ----
        float sacc[8][4];
        #pragma unroll
        for (int j = 0; j < 8; j++)
            #pragma unroll
            for (int q = 0; q < 4; q++) sacc[j][q] = 0.0f;

        #pragma unroll
        for (int ks = 0; ks < 4; ks++) {
            uint32_t kb[4][4];
            #pragma unroll
            for (int pi = 0; pi < 4; pi++)
                LDSM_X4(kb[pi][0], kb[pi][1], kb[pi][2], kb[pi][3],
                        sw_addr(Ks, pi * 16 + rin, 2 * ks + hb));
            #pragma unroll
            for (int pi = 0; pi < 4; pi++) {
                MMA_F16(sacc[2 * pi],     qf[ks], kb[pi][0], kb[pi][2]);
                MMA_F16(sacc[2 * pi + 1], qf[ks], kb[pi][1], kb[pi][3]);
            }
        }

        // ---- p = exp(s/32); accumulate l; pack P ----
        uint32_t pf[8][2];
        #pragma unroll
        for (int j = 0; j < 8; j++) {
            float p0 = __expf(sacc[j][0] * 0.03125f);
            float p1 = __expf(sacc[j][1] * 0.03125f);
            float p2 = __expf(sacc[j][2] * 0.03125f);
            float p3 = __expf(sacc[j][3] * 0.03125f);
            l0 += p0 + p1;
            l1 += p2 + p3;
            pf[j][0] = pkhf(p0, p1);
            pf[j][1] = pkhf(p2, p3);
        }

        // ---- O += P @ V  (V B-frags via ldmatrix.trans from row-major Vs) ----
        #pragma unroll
        for (int ks = 0; ks < 4; ks++) {
            uint32_t pa[4] = {pf[2 * ks][0], pf[2 * ks][1],
                              pf[2 * ks + 1][0], pf[2 * ks + 1][1]};
            #pragma unroll
            for (int pi = 0; pi < 4; pi++) {
                uint32_t vb0, vb1, vb2, vb3;
                LDSM_X4_T(vb0, vb1, vb2, vb3,
                          sw_addr(Vs, ks * 16 + rin, 2 * pi + hb));
                MMA_F16(oacc[2 * pi],     pa, vb0, vb1);
                MMA_F16(oacc[2 * pi + 1], pa, vb2, vb3);
            }
        }
        __syncthreads();
    }

    // ---- finalize: quad-reduce l, O = acc/l + Qp (fp32 residual) ----
    l0 += __shfl_xor_sync(0xffffffffu, l0, 1);
    l0 += __shfl_xor_sync(0xffffffffu, l0, 2);
    l1 += __shfl_xor_sync(0xffffffffu, l1, 1);
    l1 += __shfl_xor_sync(0xffffffffu, l1, 2);
    const float inv0 = 1.0f / l0;
    const float inv1 = 1.0f / l1;

    const int r0 = n0 + w * 16 + (lane >> 2);
    const int r1 = r0 + 8;
    #pragma unroll
    for (int j = 0; j < 8; j++) {
        const int col = j * 8 + (lane & 3) * 2;
        float2 q0 = *(const float2*)&Qp[base + (size_t)r0 * DIMD + col];
        float2 q1 = *(const float2*)&Qp[base + (size_t)r1 * DIMD + col];
        float o00 = oacc[j][0] * inv0 + q0.x;
        float o01 = oacc[j][1] * inv0 + q0.y;
        float o10 = oacc[j][2] * inv1 + q1.x;
        float o11 = oacc[j][3] * inv1 + q1.y;
        *(float2*)&Oh[base + (size_t)r0 * DIMD + col] = make_float2(o00, o01);
        *(float2*)&Oh[base + (size_t)r1 * DIMD + col] = make_float2(o10, o11);
        *(uint32_t*)&OhH[base + (size_t)r0 * DIMD + col] = pkhf(o00, o01);
        *(uint32_t*)&OhH[base + (size_t)r1 * DIMD + col] = pkhf(o10, o11);
    }
}

// ================================================================================
extern "C" void kernel_launch(void* const* d_in, const int* in_sizes, int n_in,
                              void* d_out, int out_size)
{
    const float* Q  = (const float*)d_in[0];
    const float* K  = (const float*)d_in[1];
    const float* Wq = (const float*)d_in[2];
    const float* bq = (const float*)d_in[3];
    const float* Wk = (const float*)d_in[4];
    const float* bk = (const float*)d_in[5];
    const float* Wv = (const float*)d_in[6];
    const float* bv = (const float*)d_in[7];
    const float* Wo = (const float*)d_in[8];
    const float* bo = (const float*)d_in[9];
    float* out = (float*)d_out;

    float *Qp, *Oh;
    __half *Qh, *Kh, *Vh, *OhH;
    cudaGetSymbolAddress((void**)&Qp,  g_Qp);
    cudaGetSymbolAddress((void**)&Oh,  g_Oh);
    cudaGetSymbolAddress((void**)&Qh,  g_Qh);
    cudaGetSymbolAddress((void**)&Kh,  g_Kh);
    cudaGetSymbolAddress((void**)&Vh,  g_Vh);
    cudaGetSymbolAddress((void**)&OhH, g_OhH);

    cudaFuncSetAttribute(attn_mma,
                         cudaFuncAttributeMaxDynamicSharedMemorySize, ATT_SMEM);
    cudaFuncSetAttribute(gemm_proj<0>,
                         cudaFuncAttributeMaxDynamicSharedMemorySize, GEMM_SMEM);
    cudaFuncSetAttribute(gemm_proj<1>,
                         cudaFuncAttributeMaxDynamicSharedMemorySize, GEMM_SMEM);
    cudaFuncSetAttribute(gemm_out,
                         cudaFuncAttributeMaxDynamicSharedMemorySize, GEMM_SMEM);

    dim3 gg(8, 64);
    gemm_proj<1><<<gg, 256, GEMM_SMEM>>>(Q, Wq, bq, Qp, Qh);
    gemm_proj<0><<<gg, 256, GEMM_SMEM>>>(K, Wk, bk, nullptr, Kh);
    gemm_proj<0><<<gg, 256, GEMM_SMEM>>>(K, Wv, bv, nullptr, Vh);
    attn_mma<<<dim3(16, 64), 256, ATT_SMEM>>>(Qh, Kh, Vh, Qp, Oh, OhH);
    gemm_out<<<gg, 256, GEMM_SMEM>>>(OhH, Wo, bo, Oh, out);
}